// round 14
// baseline (speedup 1.0000x reference)
#include <cuda_runtime.h>
#include <math_constants.h>

#define CB 2
#define CN 4096
#define CD 128
#define CH 4
#define CHD 32
#define CM (CB*CN)   // 8192 tokens
#define NCELL 16
#define NC2 (NCELL*NCELL)
#define CAND_CAP 2048
#define NPART 256    // bn_stats partial blocks
#define NSLICE 8     // attention partial slices: 4 j-quarters x 2 jparts

typedef unsigned long long ull;

// ---------------- f32x2 packed helpers (sm_100+ PTX) -----------------------
__device__ __forceinline__ ull ffma2(ull a, ull b, ull c) {
    ull d; asm("fma.rn.f32x2 %0,%1,%2,%3;" : "=l"(d) : "l"(a), "l"(b), "l"(c)); return d;
}
__device__ __forceinline__ ull fmul2(ull a, ull b) {
    ull d; asm("mul.rn.f32x2 %0,%1,%2;" : "=l"(d) : "l"(a), "l"(b)); return d;
}
__device__ __forceinline__ ull fadd2(ull a, ull b) {
    ull d; asm("add.rn.f32x2 %0,%1,%2;" : "=l"(d) : "l"(a), "l"(b)); return d;
}
__device__ __forceinline__ ull fpack2(float lo, float hi) {
    ull d; asm("mov.b64 %0,{%1,%2};" : "=l"(d) : "f"(lo), "f"(hi)); return d;
}
__device__ __forceinline__ void funpack2(ull a, float& lo, float& hi) {
    asm("mov.b64 {%0,%1},%2;" : "=f"(lo), "=f"(hi) : "l"(a));
}

// ---------------- cp.async helpers ------------------------------------------
__device__ __forceinline__ unsigned smem_u32(const void* p) {
    unsigned a;
    asm("{ .reg .u64 t; cvta.to.shared.u64 t, %1; cvt.u32.u64 %0, t; }" : "=r"(a) : "l"(p));
    return a;
}
__device__ __forceinline__ void cp16(unsigned s, const void* g) {
    asm volatile("cp.async.cg.shared.global [%0], [%1], 16;" :: "r"(s), "l"(g));
}
__device__ __forceinline__ void cp8(unsigned s, const void* g) {
    asm volatile("cp.async.ca.shared.global [%0], [%1], 8;" :: "r"(s), "l"(g));
}
__device__ __forceinline__ void cp4(unsigned s, const void* g) {
    asm volatile("cp.async.ca.shared.global [%0], [%1], 4;" :: "r"(s), "l"(g));
}

// ---------------- tf32 split helpers ----------------------------------------
__device__ __forceinline__ void tf32split(float x, float& hi, float& lo) {
    unsigned h;
    asm("cvt.rna.tf32.f32 %0, %1;" : "=r"(h) : "f"(x));
    float hf = __uint_as_float(h);
    float l = x - hf;
    unsigned lb;
    asm("cvt.rna.tf32.f32 %0, %1;" : "=r"(lb) : "f"(l));
    hi = hf; lo = __uint_as_float(lb);
}

__device__ __forceinline__ void mma_tf32(float* c, const unsigned* a, const unsigned* b) {
    asm volatile(
        "mma.sync.aligned.m16n8k8.row.col.f32.tf32.tf32.f32 "
        "{%0,%1,%2,%3},{%4,%5,%6,%7},{%8,%9},{%0,%1,%2,%3};\n"
        : "+f"(c[0]), "+f"(c[1]), "+f"(c[2]), "+f"(c[3])
        : "r"(a[0]), "r"(a[1]), "r"(a[2]), "r"(a[3]), "r"(b[0]), "r"(b[1]));
}

// ---------------- scratch ---------------------------------------------------
__device__ float  g_x   [CM*CD];
__device__ float  g_qkv [CM*3*CD];
__device__ float  g_hid [CM*2*CD];
__device__ float  g_partf[NPART*2*CD];
__device__ float  g_sq  [CM];
__device__ float  g_wqkv[CD*3*CD];
__device__ float  g_bqkv[3*CD];
__device__ float  g_wl1 [CD*2*CD];
__device__ float  g_bl1 [2*CD];
__device__ int    g_cstart[CB][NC2+1];
__device__ int    g_ord   [CB][CN];
__device__ int    g_cand  [CB*NC2*CAND_CAP];
__device__ float2 g_cpos  [CB*NC2*CAND_CAP];
__device__ float  g_csq   [CB*NC2*CAND_CAP];
__device__ int    g_ncand [CB*NC2];
// attention partials: [slice][token][head]
__device__ float g_pl  [NSLICE*CM*CH];
__device__ float g_pacc[NSLICE*CM*CH*32];

// ---------------- small utility kernels ------------------------------------
__global__ void copy_kernel(const float* __restrict__ src, float* __restrict__ dst, int n) {
    int i = blockIdx.x * blockDim.x + threadIdx.x;
    if (i < n) dst[i] = src[i];
}

// ---------------- fused binning: hist + scan + scatter (one block) ----------
__global__ void __launch_bounds__(1024)
bin_kernel(const float* __restrict__ pos) {
    __shared__ int scnt[CB*NC2];
    __shared__ int scur[CB*NC2];
    int tid = threadIdx.x;
    if (tid < CB*NC2) scnt[tid] = 0;
    __syncthreads();
    int mycell[8], mytok[8];
    #pragma unroll
    for (int i = 0; i < 8; ++i) {
        int t = tid + i*1024;
        int b = t >> 12, n = t & (CN-1);
        float px = pos[2*t], py = pos[2*t+1];
        int cx = min(NCELL-1, max(0, (int)(px * NCELL)));
        int cy = min(NCELL-1, max(0, (int)(py * NCELL)));
        int c = cy*NCELL + cx;
        g_sq[t] = px*px + py*py;
        mycell[i] = b*NC2 + c;
        mytok[i]  = n;
        atomicAdd(&scnt[b*NC2 + c], 1);
    }
    __syncthreads();
    int v = (tid < CB*NC2) ? scnt[tid] : 0;
    for (int off = 1; off < NC2; off <<= 1) {
        int t2 = 0;
        if (tid < CB*NC2 && (tid & (NC2-1)) >= off) t2 = scnt[tid-off];
        __syncthreads();
        if (tid < CB*NC2) scnt[tid] += t2;
        __syncthreads();
    }
    if (tid < CB*NC2) {
        int incl = scnt[tid];
        int excl = incl - v;
        int b = tid >> 8, c = tid & (NC2-1);
        g_cstart[b][c] = excl;
        scur[tid] = excl;
        if (c == NC2-1) g_cstart[b][NC2] = incl;
    }
    __syncthreads();
    #pragma unroll
    for (int i = 0; i < 8; ++i) {
        int r = atomicAdd(&scur[mycell[i]], 1);
        int b = mycell[i] >> 8;
        g_ord[b][r] = mytok[i];
    }
}

// ---------------- candidate list build: one warp per (b,cell) ---------------
// Pads lists to a multiple of 32 with sentinels (csq = +inf).
__global__ void __launch_bounds__(128)
build_cands_kernel(const float* __restrict__ pos) {
    int wid = threadIdx.x >> 5, lane = threadIdx.x & 31;
    int cidx = blockIdx.x * 4 + wid;
    int b = cidx >> 8, cell = cidx & (NC2-1);
    int cx = cell & (NCELL-1), cy = cell >> 4;
    float X0 = cx * (1.f/NCELL), X1 = (cx+1) * (1.f/NCELL);
    float Y0 = cy * (1.f/NCELL), Y1 = (cy+1) * (1.f/NCELL);
    const float R2m = 0.0625f + 1e-4f;
    int base = cidx * CAND_CAP;
    int* dst = &g_cand[base];
    int cnt = 0;
    for (int dy = -5; dy <= 5; ++dy) {
        int yy = cy + dy;
        if (yy < 0 || yy >= NCELL) continue;
        int bb = abs(dy) > 1 ? abs(dy) - 1 : 0;
        int rem = 16 - bb*bb;
        if (rem < 0) continue;
        int kx = (int)floorf(sqrtf((float)rem)) + 1;
        int x0 = cx - kx; if (x0 < 0) x0 = 0;
        int x1 = cx + kx; if (x1 > NCELL-1) x1 = NCELL-1;
        int S = g_cstart[b][yy*NCELL + x0];
        int E = g_cstart[b][yy*NCELL + x1 + 1];
        for (int j0 = S; j0 < E; j0 += 32) {
            int src = j0 + lane;
            bool keep = false; int tok = 0; float2 p = make_float2(0.f, 0.f);
            if (src < E) {
                tok = g_ord[b][src];
                p = ((const float2*)pos)[b*CN + tok];
                float ddx = fmaxf(fmaxf(X0 - p.x, p.x - X1), 0.f);
                float ddy = fmaxf(fmaxf(Y0 - p.y, p.y - Y1), 0.f);
                keep = (ddx*ddx + ddy*ddy) <= R2m;
            }
            unsigned bal = __ballot_sync(0xFFFFFFFFu, keep);
            int ofs = __popc(bal & ((1u << lane) - 1));
            if (keep && cnt + ofs < CAND_CAP) {
                int w = cnt + ofs;
                dst[w] = tok;
                g_cpos[base + w] = p;
                g_csq[base + w] = p.x*p.x + p.y*p.y;
            }
            cnt += __popc(bal);
        }
    }
    if (cnt > CAND_CAP) cnt = CAND_CAP;
    int padded = (cnt + 31) & ~31;
    if (padded > CAND_CAP) padded = CAND_CAP;
    for (int i2 = cnt + lane; i2 < padded; i2 += 32) {
        dst[i2] = 0;
        g_cpos[base + i2] = make_float2(0.f, 0.f);
        g_csq[base + i2] = CUDART_INF_F;
    }
    if (lane == 0) g_ncand[cidx] = padded;
}

// ---------------- BatchNorm stats (fp32 partials, wide grid) -----------------
__global__ void __launch_bounds__(128)
bn_stats_kernel(const float* __restrict__ x, float* __restrict__ part) {
    int d = threadIdx.x;
    int blk = blockIdx.x;
    int r0 = blk * (CM / NPART);
    float s = 0.f, s2 = 0.f;
    #pragma unroll 8
    for (int r = 0; r < CM/NPART; ++r) {
        float v = x[(r0 + r)*CD + d];
        s  += v;
        s2 += v*v;
    }
    part[blk*2*CD + d]      = s;
    part[blk*2*CD + CD + d] = s2;
}

// ---------------- BN-folded weight transforms -------------------------------
__device__ __forceinline__ void bn_finalize_smem(const float* gam, const float* bet,
                                                 float* sa, float* sc, int tid) {
    if (tid < CD) {
        double s0=0,s1=0,s2d=0,s3=0,q0=0,q1=0,q2=0,q3=0;
        #pragma unroll 4
        for (int b2 = 0; b2 < NPART; b2 += 4) {
            s0 += (double)g_partf[(b2+0)*2*CD + tid];  q0 += (double)g_partf[(b2+0)*2*CD + CD + tid];
            s1 += (double)g_partf[(b2+1)*2*CD + tid];  q1 += (double)g_partf[(b2+1)*2*CD + CD + tid];
            s2d+= (double)g_partf[(b2+2)*2*CD + tid];  q2 += (double)g_partf[(b2+2)*2*CD + CD + tid];
            s3 += (double)g_partf[(b2+3)*2*CD + tid];  q3 += (double)g_partf[(b2+3)*2*CD + CD + tid];
        }
        double s = (s0+s1)+(s2d+s3);
        double sq = (q0+q1)+(q2+q3);
        double m   = s / (double)CM;
        double var = sq / (double)CM - m*m;
        float rstd = rsqrtf((float)var + 1e-5f);
        float a = rstd * gam[tid];
        sa[tid] = a;
        sc[tid] = bet[tid] - (float)m * a;
    }
}

__global__ void __launch_bounds__(256)
xform_qkv_kernel(const float* __restrict__ Wq, const float* __restrict__ Wk,
                 const float* __restrict__ Wv,
                 const float* __restrict__ bq, const float* __restrict__ bk,
                 const float* __restrict__ bv,
                 const float* __restrict__ gam, const float* __restrict__ bet) {
    __shared__ float sa[CD], sc[CD];
    int tid = threadIdx.x;
    bn_finalize_smem(gam, bet, sa, sc, tid);
    __syncthreads();
    int nb = blockIdx.x * 64;
    {
        int n = nb + (tid & 63);
        int sel = n >> 7, ci = n & (CD-1);
        const float* W = (sel == 0) ? Wq : (sel == 1) ? Wk : Wv;
        for (int k = tid >> 6; k < CD; k += 4)
            g_wqkv[k*384 + n] = sa[k] * W[k*CD + ci];
    }
    if (tid < 64) {
        int n2 = nb + tid;
        int sel2 = n2 >> 7, ci2 = n2 & (CD-1);
        const float* W2 = (sel2 == 0) ? Wq : (sel2 == 1) ? Wk : Wv;
        const float* bb = (sel2 == 0) ? bq : (sel2 == 1) ? bk : bv;
        float s = 0.f;
        #pragma unroll 4
        for (int k = 0; k < CD; ++k) s += sc[k] * W2[k*CD + ci2];
        g_bqkv[n2] = bb[ci2] + s;
    }
}

__global__ void __launch_bounds__(256)
xform_l1_kernel(const float* __restrict__ W, const float* __restrict__ bias,
                const float* __restrict__ gam, const float* __restrict__ bet) {
    __shared__ float sa[CD], sc[CD];
    int tid = threadIdx.x;
    bn_finalize_smem(gam, bet, sa, sc, tid);
    __syncthreads();
    int nb = blockIdx.x * 64;
    {
        int n = nb + (tid & 63);
        for (int k = tid >> 6; k < CD; k += 4)
            g_wl1[k*(2*CD) + n] = sa[k] * W[k*(2*CD) + n];
    }
    if (tid < 64) {
        int n2 = nb + tid;
        float s = 0.f;
        #pragma unroll 4
        for (int k = 0; k < CD; ++k) s += sc[k] * W[k*(2*CD) + n2];
        g_bl1[n2] = bias[n2] + s;
    }
}

// ---------------- RoPE (layer 0 only) ---------------------------------------
__global__ void rope_kernel(float* __restrict__ qkv, const float* __restrict__ pos) {
    int idx = blockIdx.x * blockDim.x + threadIdx.x;
    if (idx >= CM * 64) return;
    int p = idx & 63;
    int t = idx >> 6;
    int group = p >> 5;
    int fidx  = p & 31;
    float freq = 3.14159265358979324f * (float)(fidx + 1);
    float ang = pos[t*2 + group] * freq;
    float sv, cv;
    sincosf(ang, &sv, &cv);
    int qb = t*3*CD + (p << 1);
    float q0 = qkv[qb], q1 = qkv[qb+1];
    qkv[qb]   = cv*q0 - sv*q1;
    qkv[qb+1] = cv*q1 + sv*q0;
    int kb = qb + CD;
    float k0 = qkv[kb], k1 = qkv[kb+1];
    qkv[kb]   = cv*k0 - sv*k1;
    qkv[kb+1] = cv*k1 + sv*k0;
}

// ---------------- tensor-core GEMM (3xTF32) ---------------------------------
#define AS_STR 36
#define BS_STR 72
#define SM_AHI 0
#define SM_ALO (128*AS_STR)
#define SM_BHI (2*128*AS_STR)
#define SM_BLO (2*128*AS_STR + 32*BS_STR)
#define GEMM_SMEM ((2*128*AS_STR + 2*32*BS_STR)*4)

__global__ void __launch_bounds__(256)
gemm_tc_kernel(const float* __restrict__ A, const float* __restrict__ W,
               const float* __restrict__ bias, const float* __restrict__ resid,
               float* __restrict__ C, int M, int K, int Nout, int relu, int mergeA) {
    extern __shared__ float sm[];
    float* As_hi = sm + SM_AHI;
    float* As_lo = sm + SM_ALO;
    float* Bs_hi = sm + SM_BHI;
    float* Bs_lo = sm + SM_BLO;

    int tid = threadIdx.x;
    int lane = tid & 31, warp = tid >> 5;
    int wm = warp & 3, wn = warp >> 2;
    int m_w = wm*32, n_w = wn*32;
    int g = lane >> 2, t = lane & 3;

    int bm0 = blockIdx.x * 128, bn0 = blockIdx.y * 64;

    float acc[2][4][4];
    #pragma unroll
    for (int i = 0; i < 2; ++i)
        #pragma unroll
        for (int j = 0; j < 4; ++j)
            #pragma unroll
            for (int u = 0; u < 4; ++u) acc[i][j][u] = 0.f;

    for (int k0 = 0; k0 < K; k0 += 32) {
        __syncthreads();
        #pragma unroll
        for (int it = 0; it < 4; ++it) {
            int f = tid + it*256;
            int row = f >> 3, c4 = (f & 7) << 2;
            float4 ga;
            if (mergeA) {
                int t_tok = bm0 + row;
                int kcol = k0 + c4;
                int head = kcol >> 5, d0 = kcol & 31;
                int i0 = t_tok*CH + head;
                float lsum = 0.f;
                float4 vs = make_float4(0.f, 0.f, 0.f, 0.f);
                #pragma unroll
                for (int sl2 = 0; sl2 < NSLICE; ++sl2) {
                    float4 v = *(const float4*)&g_pacc[((ull)sl2*CM*CH + i0)*32 + d0];
                    vs.x += v.x; vs.y += v.y; vs.z += v.z; vs.w += v.w;
                    lsum += g_pl[sl2*CM*CH + i0];
                }
                float f0 = 1.f / lsum;
                ga.x = vs.x*f0; ga.y = vs.y*f0; ga.z = vs.z*f0; ga.w = vs.w*f0;
            } else {
                ga = *(const float4*)&A[(bm0 + row)*K + k0 + c4];
            }
            float4 h4, l4;
            tf32split(ga.x, h4.x, l4.x);
            tf32split(ga.y, h4.y, l4.y);
            tf32split(ga.z, h4.z, l4.z);
            tf32split(ga.w, h4.w, l4.w);
            *(float4*)&As_hi[row*AS_STR + c4] = h4;
            *(float4*)&As_lo[row*AS_STR + c4] = l4;
        }
        #pragma unroll
        for (int it = 0; it < 2; ++it) {
            int f = tid + it*256;
            int row = f >> 4, c4 = (f & 15) << 2;
            float4 gb = *(const float4*)&W[(k0 + row)*Nout + bn0 + c4];
            float4 h4, l4;
            tf32split(gb.x, h4.x, l4.x);
            tf32split(gb.y, h4.y, l4.y);
            tf32split(gb.z, h4.z, l4.z);
            tf32split(gb.w, h4.w, l4.w);
            *(float4*)&Bs_hi[row*BS_STR + c4] = h4;
            *(float4*)&Bs_lo[row*BS_STR + c4] = l4;
        }
        __syncthreads();

        #pragma unroll
        for (int k8 = 0; k8 < 32; k8 += 8) {
            unsigned ah[2][4], al[2][4];
            #pragma unroll
            for (int mt = 0; mt < 2; ++mt) {
                int base = (m_w + mt*16 + g)*AS_STR + k8 + t;
                ah[mt][0] = __float_as_uint(As_hi[base]);
                ah[mt][1] = __float_as_uint(As_hi[base + 8*AS_STR]);
                ah[mt][2] = __float_as_uint(As_hi[base + 4]);
                ah[mt][3] = __float_as_uint(As_hi[base + 8*AS_STR + 4]);
                al[mt][0] = __float_as_uint(As_lo[base]);
                al[mt][1] = __float_as_uint(As_lo[base + 8*AS_STR]);
                al[mt][2] = __float_as_uint(As_lo[base + 4]);
                al[mt][3] = __float_as_uint(As_lo[base + 8*AS_STR + 4]);
            }
            unsigned bh[4][2], bl[4][2];
            #pragma unroll
            for (int nt = 0; nt < 4; ++nt) {
                int base = (k8 + t)*BS_STR + n_w + nt*8 + g;
                bh[nt][0] = __float_as_uint(Bs_hi[base]);
                bh[nt][1] = __float_as_uint(Bs_hi[base + 4*BS_STR]);
                bl[nt][0] = __float_as_uint(Bs_lo[base]);
                bl[nt][1] = __float_as_uint(Bs_lo[base + 4*BS_STR]);
            }
            #pragma unroll
            for (int mt = 0; mt < 2; ++mt)
                #pragma unroll
                for (int nt = 0; nt < 4; ++nt) {
                    mma_tf32(acc[mt][nt], al[mt], bh[nt]);
                    mma_tf32(acc[mt][nt], ah[mt], bl[nt]);
                    mma_tf32(acc[mt][nt], ah[mt], bh[nt]);
                }
        }
    }

    #pragma unroll
    for (int mt = 0; mt < 2; ++mt) {
        #pragma unroll
        for (int nt = 0; nt < 4; ++nt) {
            int row0 = bm0 + m_w + mt*16 + g;
            int col  = bn0 + n_w + nt*8 + 2*t;
            float2 bv = *(const float2*)&bias[col];
            float2 r0, r1;
            r0.x = acc[mt][nt][0] + bv.x;  r0.y = acc[mt][nt][1] + bv.y;
            r1.x = acc[mt][nt][2] + bv.x;  r1.y = acc[mt][nt][3] + bv.y;
            if (resid) {
                float2 v0 = *(const float2*)&resid[row0*Nout + col];
                float2 v1 = *(const float2*)&resid[(row0+8)*Nout + col];
                r0.x += v0.x; r0.y += v0.y;
                r1.x += v1.x; r1.y += v1.y;
            }
            if (relu) {
                r0.x = fmaxf(r0.x, 0.f); r0.y = fmaxf(r0.y, 0.f);
                r1.x = fmaxf(r1.x, 0.f); r1.y = fmaxf(r1.y, 0.f);
            }
            *(float2*)&C[row0*Nout + col]     = r0;
            *(float2*)&C[(row0+8)*Nout + col] = r1;
        }
    }
}

// ---------------- attention: 128 threads, j-quarters x warp-pair split ------
// grid (NC2, 2 qtiles, CB*4 jquarters); 128 threads = 2 jparts x (16 slots x 4 heads).
#define TJR 16
#define KS_OFF 0
#define VS_OFF (2*TJR*128)
#define PS_OFF (4*TJR*128)
#define SS_OFF (4*TJR*128 + 2*2*TJR)
#define ATTN_SMEM ((4*TJR*128 + 2*2*TJR + 2*TJR)*4)

__global__ void __launch_bounds__(128)
attn_kernel(const float* __restrict__ qkv, const float* __restrict__ pos,
            const float* __restrict__ sqv) {
    extern __shared__ float smn[];

    int cell = blockIdx.x, qt = blockIdx.y;
    int b = blockIdx.z >> 2, jq = blockIdx.z & 3;
    int cidx = b*NC2 + cell;
    int cstart = g_cstart[b][cell];
    int ccount = g_cstart[b][cell+1] - cstart;
    if (qt*16 >= ccount) return;

    int ncand = g_ncand[cidx];          // multiple of 32
    int cbase = cidx*CAND_CAP;
    const int* cand = &g_cand[cbase];
    int nt32 = ncand >> 5;
    int jstart = ((nt32 * jq) >> 2) * 32;
    int jend   = ((nt32 * (jq+1)) >> 2) * 32;

    int tid  = threadIdx.x;
    int w    = tid >> 5, lane = tid & 31;
    int jpart = w >> 1;
    int slot = lane & 15;
    int head = ((w & 1) << 1) | (lane >> 4);
    int slice = jq*2 + jpart;

    if (jstart >= jend) {               // empty quarter: zero partials
        for (int q0 = qt*16; q0 < ccount; q0 += 32) {
            if ((q0 + slot) < ccount) {
                int qi = g_ord[b][cstart + q0 + slot];
                int t = b*CN + qi;
                int pidx = (slice*CM + t)*CH + head;
                g_pl[pidx] = 0.f;
                ulonglong2* ap = (ulonglong2*)&g_pacc[(ull)pidx*32];
                ulonglong2 z; z.x = 0ull; z.y = 0ull;
                #pragma unroll
                for (int u = 0; u < 8; ++u) ap[u] = z;
            }
        }
        return;
    }
    int ntiles = (jend - jstart + TJR - 1) / TJR;

    unsigned sb = smem_u32(smn);

    // scale folded with log2(e): softmax exp(s) = exp2(s * log2e)
    const float scale = 0.17677669529663687f * 1.4426950408889634f;
    const float R2 = 0.0625f;
    ull scale2 = fpack2(scale, scale);

    for (int q0 = qt*16; q0 < ccount; q0 += 32) {
        bool active = (q0 + slot) < ccount;
        int qidx = active ? (q0 + slot) : 0;
        int qi = g_ord[b][cstart + qidx];
        int t = b*CN + qi;

        ull qr2[16];
        const ulonglong2* qp = (const ulonglong2*)&qkv[t*3*CD + head*CHD];
        #pragma unroll
        for (int u = 0; u < 8; ++u) {
            ulonglong2 qq = qp[u];
            qr2[2*u]   = fmul2(qq.x, scale2);
            qr2[2*u+1] = fmul2(qq.y, scale2);
        }
        float2 pi  = ((const float2*)pos)[t];
        float  sqi = sqv[t];

        float l = 0.f;
        ull acc2[16];
        #pragma unroll
        for (int u = 0; u < 16; ++u) acc2[u] = 0ull;

        // prologue: stage tile 0 (4 warps x 4 rows)
        {
            int ts = jstart;
            #pragma unroll
            for (int rr = 0; rr < TJR/4; ++rr) {
                int r = w + rr*4;
                int tj = b*CN + cand[ts + r];
                const char* gk = (const char*)&qkv[tj*3*CD + CD];
                const char* gv = (const char*)&qkv[tj*3*CD + 2*CD];
                cp16(sb + (KS_OFF + r*128)*4 + lane*16, gk + lane*16);
                cp16(sb + (VS_OFF + r*128)*4 + lane*16, gv + lane*16);
            }
            if (tid < TJR) {
                cp8(sb + (PS_OFF + tid*2)*4, &g_cpos[cbase + ts + tid]);
                cp4(sb + (SS_OFF + tid)*4,   &g_csq [cbase + ts + tid]);
            }
            asm volatile("cp.async.commit_group;" ::: "memory");
        }

        for (int tl = 0; tl < ntiles; ++tl) {
            int cur = tl & 1;
            if (tl + 1 < ntiles) {
                int nb2 = (tl + 1) & 1;
                int ts = jstart + (tl+1)*TJR;
                #pragma unroll
                for (int rr = 0; rr < TJR/4; ++rr) {
                    int r = w + rr*4;
                    int tj = b*CN + cand[ts + r];
                    const char* gk = (const char*)&qkv[tj*3*CD + CD];
                    const char* gv = (const char*)&qkv[tj*3*CD + 2*CD];
                    cp16(sb + (KS_OFF + nb2*TJR*128 + r*128)*4 + lane*16, gk + lane*16);
                    cp16(sb + (VS_OFF + nb2*TJR*128 + r*128)*4 + lane*16, gv + lane*16);
                }
                if (tid < TJR) {
                    cp8(sb + (PS_OFF + nb2*2*TJR + tid*2)*4, &g_cpos[cbase + ts + tid]);
                    cp4(sb + (SS_OFF + nb2*TJR + tid)*4,     &g_csq [cbase + ts + tid]);
                }
                asm volatile("cp.async.commit_group;" ::: "memory");
                asm volatile("cp.async.wait_group 1;" ::: "memory");
            } else {
                asm volatile("cp.async.wait_group 0;" ::: "memory");
            }
            __syncthreads();

            const float*  Kb = smn + KS_OFF + cur*TJR*128;
            const float*  Vb = smn + VS_OFF + cur*TJR*128;
            const float2* Pb = (const float2*)(smn + PS_OFF + cur*2*TJR);
            const float*  Sb = smn + SS_OFF + cur*TJR;

            #pragma unroll
            for (int j0j = 0; j0j < TJR/2; ++j0j) {
                int j = jpart*(TJR/2) + j0j;
                float2 pj = Pb[j];
                float d2 = sqi + Sb[j] - 2.f*(pi.x*pj.x + pi.y*pj.y);
                bool inw = (d2 <= R2);

                const ulonglong2* kr = (const ulonglong2*)&Kb[j*128 + (head<<5)];
                ulonglong2 k0v = kr[0], k1v = kr[1], k2v = kr[2], k3v = kr[3];
                ull sa  = fmul2(qr2[0],  k0v.x);
                ull sb2 = fmul2(qr2[1],  k0v.y);
                ull sc2 = fmul2(qr2[2],  k1v.x);
                ull sd  = fmul2(qr2[3],  k1v.y);
                sa  = ffma2(qr2[4],  k2v.x, sa);
                sb2 = ffma2(qr2[5],  k2v.y, sb2);
                sc2 = ffma2(qr2[6],  k3v.x, sc2);
                sd  = ffma2(qr2[7],  k3v.y, sd);
                ulonglong2 k4v = kr[4], k5v = kr[5], k6v = kr[6], k7v = kr[7];
                sa  = ffma2(qr2[8],  k4v.x, sa);
                sb2 = ffma2(qr2[9],  k4v.y, sb2);
                sc2 = ffma2(qr2[10], k5v.x, sc2);
                sd  = ffma2(qr2[11], k5v.y, sd);
                sa  = ffma2(qr2[12], k6v.x, sa);
                sb2 = ffma2(qr2[13], k6v.y, sb2);
                sc2 = ffma2(qr2[14], k7v.x, sc2);
                sd  = ffma2(qr2[15], k7v.y, sd);
                float sl, sh;
                funpack2(fadd2(fadd2(sa, sb2), fadd2(sc2, sd)), sl, sh);
                float s = sl + sh;

                float pb = inw ? exp2f(s) : 0.f;
                l += pb;
                ull pb2 = fpack2(pb, pb);
                const ulonglong2* vr = (const ulonglong2*)&Vb[j*128 + (head<<5)];
                #pragma unroll
                for (int u = 0; u < 8; ++u) {
                    ulonglong2 vv = vr[u];
                    acc2[2*u]   = ffma2(pb2, vv.x, acc2[2*u]);
                    acc2[2*u+1] = ffma2(pb2, vv.y, acc2[2*u+1]);
                }
            }
            __syncthreads();
        }

        if (active) {
            int pidx = (slice*CM + t)*CH + head;
            g_pl[pidx] = l;
            ulonglong2* ap = (ulonglong2*)&g_pacc[(ull)pidx*32];
            #pragma unroll
            for (int u = 0; u < 8; ++u) {
                ulonglong2 wv; wv.x = acc2[2*u]; wv.y = acc2[2*u+1];
                ap[u] = wv;
            }
        }
    }
}

// ---------------- launch ----------------------------------------------------
extern "C" void kernel_launch(void* const* d_in, const int* in_sizes, int n_in,
                              void* d_out, int out_size) {
    const float* x    = (const float*)d_in[0];
    const float* pos  = (const float*)d_in[1];
    const float* Wq_w = (const float*)d_in[2];
    const float* Wq_b = (const float*)d_in[3];
    const float* Wk_w = (const float*)d_in[4];
    const float* Wk_b = (const float*)d_in[5];
    const float* Wv_w = (const float*)d_in[6];
    const float* Wv_b = (const float*)d_in[7];
    const float* Wo_w = (const float*)d_in[8];
    const float* Wo_b = (const float*)d_in[9];
    const float* n1_g = (const float*)d_in[10];
    const float* n1_b = (const float*)d_in[11];
    const float* n2_g = (const float*)d_in[12];
    const float* n2_b = (const float*)d_in[13];
    const float* l1_w = (const float*)d_in[14];
    const float* l1_b = (const float*)d_in[15];
    const float* l2_w = (const float*)d_in[16];
    const float* l2_b = (const float*)d_in[17];
    float* out = (float*)d_out;

    float *gx, *gqkv, *ghid, *gwqkv, *gbqkv, *gwl1, *gbl1, *gsq, *gpartf;
    cudaGetSymbolAddress((void**)&gx,    g_x);
    cudaGetSymbolAddress((void**)&gqkv,  g_qkv);
    cudaGetSymbolAddress((void**)&ghid,  g_hid);
    cudaGetSymbolAddress((void**)&gpartf,g_partf);
    cudaGetSymbolAddress((void**)&gwqkv, g_wqkv);
    cudaGetSymbolAddress((void**)&gbqkv, g_bqkv);
    cudaGetSymbolAddress((void**)&gwl1,  g_wl1);
    cudaGetSymbolAddress((void**)&gbl1,  g_bl1);
    cudaGetSymbolAddress((void**)&gsq,   g_sq);

    cudaFuncSetAttribute(gemm_tc_kernel,
                         cudaFuncAttributeMaxDynamicSharedMemorySize, GEMM_SMEM);
    cudaFuncSetAttribute(attn_kernel,
                         cudaFuncAttributeMaxDynamicSharedMemorySize, ATTN_SMEM);

    dim3 gP(CM/128, CD/64);
    dim3 gQKV(CM/128, 3*CD/64);
    dim3 gF(CM/128, 2*CD/64);

    copy_kernel<<<(CM*CD + 255)/256, 256>>>(x, gx, CM*CD);
    bin_kernel<<<1, 1024>>>(pos);
    build_cands_kernel<<<CB*NC2/4, 128>>>(pos);

    for (int i = 0; i < 2; ++i) {
        const float* xin = (i == 0) ? x : gx;

        // --- attention block (BN folded into QKV weights) ---
        bn_stats_kernel<<<NPART, 128>>>(xin, gpartf);
        xform_qkv_kernel<<<6, 256>>>(Wq_w + i*CD*CD, Wk_w + i*CD*CD, Wv_w + i*CD*CD,
                                     Wq_b + i*CD, Wk_b + i*CD, Wv_b + i*CD,
                                     n1_g + i*CD, n1_b + i*CD);
        gemm_tc_kernel<<<gQKV, 256, GEMM_SMEM>>>(xin, gwqkv, gbqkv, nullptr, gqkv,
                                                 CM, CD, 3*CD, 0, 0);
        if (i == 0)
            rope_kernel<<<(CM*64 + 255)/256, 256>>>(gqkv, pos);

        attn_kernel<<<dim3(NC2, 2, CB*4), 128, ATTN_SMEM>>>(gqkv, pos, gsq);
        gemm_tc_kernel<<<gP, 256, GEMM_SMEM>>>(nullptr, Wo_w + i*CD*CD, Wo_b + i*CD,
                                               gx, gx, CM, CD, CD, 0, 1);

        // --- FFN block (BN folded into l1 weights) ---
        bn_stats_kernel<<<NPART, 128>>>(gx, gpartf);
        xform_l1_kernel<<<4, 256>>>(l1_w + i*CD*2*CD, l1_b + i*2*CD,
                                    n2_g + i*CD, n2_b + i*CD);
        gemm_tc_kernel<<<gF, 256, GEMM_SMEM>>>(gx, gwl1, gbl1, nullptr, ghid,
                                               CM, CD, 2*CD, 1, 0);
        float* dst = (i == 1) ? out : gx;
        gemm_tc_kernel<<<gP, 256, GEMM_SMEM>>>(ghid, l2_w + i*2*CD*CD, l2_b + i*CD,
                                               gx, dst, CM, 2*CD, CD, 0, 0);
    }
}

// round 15
// speedup vs baseline: 1.0209x; 1.0209x over previous
#include <cuda_runtime.h>
#include <math_constants.h>

#define CB 2
#define CN 4096
#define CD 128
#define CH 4
#define CHD 32
#define CM (CB*CN)   // 8192 tokens
#define NCELL 16
#define NC2 (NCELL*NCELL)
#define CAND_CAP 2048
#define NPART 256    // bn_stats partial blocks
#define NSLICE 4     // attention partial slices: 2 j-halves x 2 jparts

typedef unsigned long long ull;

// ---------------- f32x2 packed helpers (sm_100+ PTX) -----------------------
__device__ __forceinline__ ull ffma2(ull a, ull b, ull c) {
    ull d; asm("fma.rn.f32x2 %0,%1,%2,%3;" : "=l"(d) : "l"(a), "l"(b), "l"(c)); return d;
}
__device__ __forceinline__ ull fmul2(ull a, ull b) {
    ull d; asm("mul.rn.f32x2 %0,%1,%2;" : "=l"(d) : "l"(a), "l"(b)); return d;
}
__device__ __forceinline__ ull fadd2(ull a, ull b) {
    ull d; asm("add.rn.f32x2 %0,%1,%2;" : "=l"(d) : "l"(a), "l"(b)); return d;
}
__device__ __forceinline__ ull fpack2(float lo, float hi) {
    ull d; asm("mov.b64 %0,{%1,%2};" : "=l"(d) : "f"(lo), "f"(hi)); return d;
}
__device__ __forceinline__ void funpack2(ull a, float& lo, float& hi) {
    asm("mov.b64 {%0,%1},%2;" : "=f"(lo), "=f"(hi) : "l"(a));
}

// ---------------- cp.async helpers ------------------------------------------
__device__ __forceinline__ unsigned smem_u32(const void* p) {
    unsigned a;
    asm("{ .reg .u64 t; cvta.to.shared.u64 t, %1; cvt.u32.u64 %0, t; }" : "=r"(a) : "l"(p));
    return a;
}
__device__ __forceinline__ void cp16(unsigned s, const void* g) {
    asm volatile("cp.async.cg.shared.global [%0], [%1], 16;" :: "r"(s), "l"(g));
}
__device__ __forceinline__ void cp8(unsigned s, const void* g) {
    asm volatile("cp.async.ca.shared.global [%0], [%1], 8;" :: "r"(s), "l"(g));
}
__device__ __forceinline__ void cp4(unsigned s, const void* g) {
    asm volatile("cp.async.ca.shared.global [%0], [%1], 4;" :: "r"(s), "l"(g));
}

// ---------------- tf32 split helpers ----------------------------------------
__device__ __forceinline__ void tf32split(float x, float& hi, float& lo) {
    unsigned h;
    asm("cvt.rna.tf32.f32 %0, %1;" : "=r"(h) : "f"(x));
    float hf = __uint_as_float(h);
    float l = x - hf;
    unsigned lb;
    asm("cvt.rna.tf32.f32 %0, %1;" : "=r"(lb) : "f"(l));
    hi = hf; lo = __uint_as_float(lb);
}

__device__ __forceinline__ void mma_tf32(float* c, const unsigned* a, const unsigned* b) {
    asm volatile(
        "mma.sync.aligned.m16n8k8.row.col.f32.tf32.tf32.f32 "
        "{%0,%1,%2,%3},{%4,%5,%6,%7},{%8,%9},{%0,%1,%2,%3};\n"
        : "+f"(c[0]), "+f"(c[1]), "+f"(c[2]), "+f"(c[3])
        : "r"(a[0]), "r"(a[1]), "r"(a[2]), "r"(a[3]), "r"(b[0]), "r"(b[1]));
}

// ---------------- scratch ---------------------------------------------------
__device__ float  g_x   [CM*CD];
__device__ float  g_qkv [CM*3*CD];
__device__ float  g_hid [CM*2*CD];
__device__ float  g_partf[NPART*2*CD];
__device__ float  g_sq  [CM];
__device__ float  g_wqkv[CD*3*CD];
__device__ float  g_bqkv[3*CD];
__device__ float  g_wl1 [CD*2*CD];
__device__ float  g_bl1 [2*CD];
__device__ int    g_cstart[CB][NC2+1];
__device__ int    g_ord   [CB][CN];
__device__ int    g_cand  [CB*NC2*CAND_CAP];
__device__ float2 g_cpos  [CB*NC2*CAND_CAP];
__device__ float  g_csq   [CB*NC2*CAND_CAP];
__device__ int    g_ncand [CB*NC2];
// attention partials: [slice][token][head]
__device__ float g_pl  [NSLICE*CM*CH];
__device__ float g_pacc[NSLICE*CM*CH*32];

// ---------------- small utility kernels ------------------------------------
__global__ void copy_kernel(const float* __restrict__ src, float* __restrict__ dst, int n) {
    int i = blockIdx.x * blockDim.x + threadIdx.x;
    if (i < n) dst[i] = src[i];
}

// ---------------- fused binning: hist + scan + scatter (one block) ----------
__global__ void __launch_bounds__(1024)
bin_kernel(const float* __restrict__ pos) {
    __shared__ int scnt[CB*NC2];
    __shared__ int scur[CB*NC2];
    int tid = threadIdx.x;
    if (tid < CB*NC2) scnt[tid] = 0;
    __syncthreads();
    int mycell[8], mytok[8];
    #pragma unroll
    for (int i = 0; i < 8; ++i) {
        int t = tid + i*1024;
        int b = t >> 12, n = t & (CN-1);
        float px = pos[2*t], py = pos[2*t+1];
        int cx = min(NCELL-1, max(0, (int)(px * NCELL)));
        int cy = min(NCELL-1, max(0, (int)(py * NCELL)));
        int c = cy*NCELL + cx;
        g_sq[t] = px*px + py*py;
        mycell[i] = b*NC2 + c;
        mytok[i]  = n;
        atomicAdd(&scnt[b*NC2 + c], 1);
    }
    __syncthreads();
    int v = (tid < CB*NC2) ? scnt[tid] : 0;
    for (int off = 1; off < NC2; off <<= 1) {
        int t2 = 0;
        if (tid < CB*NC2 && (tid & (NC2-1)) >= off) t2 = scnt[tid-off];
        __syncthreads();
        if (tid < CB*NC2) scnt[tid] += t2;
        __syncthreads();
    }
    if (tid < CB*NC2) {
        int incl = scnt[tid];
        int excl = incl - v;
        int b = tid >> 8, c = tid & (NC2-1);
        g_cstart[b][c] = excl;
        scur[tid] = excl;
        if (c == NC2-1) g_cstart[b][NC2] = incl;
    }
    __syncthreads();
    #pragma unroll
    for (int i = 0; i < 8; ++i) {
        int r = atomicAdd(&scur[mycell[i]], 1);
        int b = mycell[i] >> 8;
        g_ord[b][r] = mytok[i];
    }
}

// ---------------- candidate list build: one warp per (b,cell) ---------------
// Pads lists to a multiple of 32 with sentinels (csq = +inf).
__global__ void __launch_bounds__(128)
build_cands_kernel(const float* __restrict__ pos) {
    int wid = threadIdx.x >> 5, lane = threadIdx.x & 31;
    int cidx = blockIdx.x * 4 + wid;
    int b = cidx >> 8, cell = cidx & (NC2-1);
    int cx = cell & (NCELL-1), cy = cell >> 4;
    float X0 = cx * (1.f/NCELL), X1 = (cx+1) * (1.f/NCELL);
    float Y0 = cy * (1.f/NCELL), Y1 = (cy+1) * (1.f/NCELL);
    const float R2m = 0.0625f + 1e-4f;
    int base = cidx * CAND_CAP;
    int* dst = &g_cand[base];
    int cnt = 0;
    for (int dy = -5; dy <= 5; ++dy) {
        int yy = cy + dy;
        if (yy < 0 || yy >= NCELL) continue;
        int bb = abs(dy) > 1 ? abs(dy) - 1 : 0;
        int rem = 16 - bb*bb;
        if (rem < 0) continue;
        int kx = (int)floorf(sqrtf((float)rem)) + 1;
        int x0 = cx - kx; if (x0 < 0) x0 = 0;
        int x1 = cx + kx; if (x1 > NCELL-1) x1 = NCELL-1;
        int S = g_cstart[b][yy*NCELL + x0];
        int E = g_cstart[b][yy*NCELL + x1 + 1];
        for (int j0 = S; j0 < E; j0 += 32) {
            int src = j0 + lane;
            bool keep = false; int tok = 0; float2 p = make_float2(0.f, 0.f);
            if (src < E) {
                tok = g_ord[b][src];
                p = ((const float2*)pos)[b*CN + tok];
                float ddx = fmaxf(fmaxf(X0 - p.x, p.x - X1), 0.f);
                float ddy = fmaxf(fmaxf(Y0 - p.y, p.y - Y1), 0.f);
                keep = (ddx*ddx + ddy*ddy) <= R2m;
            }
            unsigned bal = __ballot_sync(0xFFFFFFFFu, keep);
            int ofs = __popc(bal & ((1u << lane) - 1));
            if (keep && cnt + ofs < CAND_CAP) {
                int w = cnt + ofs;
                dst[w] = tok;
                g_cpos[base + w] = p;
                g_csq[base + w] = p.x*p.x + p.y*p.y;
            }
            cnt += __popc(bal);
        }
    }
    if (cnt > CAND_CAP) cnt = CAND_CAP;
    int padded = (cnt + 31) & ~31;
    if (padded > CAND_CAP) padded = CAND_CAP;
    for (int i2 = cnt + lane; i2 < padded; i2 += 32) {
        dst[i2] = 0;
        g_cpos[base + i2] = make_float2(0.f, 0.f);
        g_csq[base + i2] = CUDART_INF_F;
    }
    if (lane == 0) g_ncand[cidx] = padded;
}

// ---------------- BatchNorm stats (fp32 partials, wide grid) -----------------
__global__ void __launch_bounds__(128)
bn_stats_kernel(const float* __restrict__ x, float* __restrict__ part) {
    int d = threadIdx.x;
    int blk = blockIdx.x;
    int r0 = blk * (CM / NPART);
    float s = 0.f, s2 = 0.f;
    #pragma unroll 8
    for (int r = 0; r < CM/NPART; ++r) {
        float v = x[(r0 + r)*CD + d];
        s  += v;
        s2 += v*v;
    }
    part[blk*2*CD + d]      = s;
    part[blk*2*CD + CD + d] = s2;
}

// ---------------- BN-folded weight transforms -------------------------------
__device__ __forceinline__ void bn_finalize_smem(const float* gam, const float* bet,
                                                 float* sa, float* sc, int tid) {
    if (tid < CD) {
        double s0=0,s1=0,s2d=0,s3=0,q0=0,q1=0,q2=0,q3=0;
        #pragma unroll 4
        for (int b2 = 0; b2 < NPART; b2 += 4) {
            s0 += (double)g_partf[(b2+0)*2*CD + tid];  q0 += (double)g_partf[(b2+0)*2*CD + CD + tid];
            s1 += (double)g_partf[(b2+1)*2*CD + tid];  q1 += (double)g_partf[(b2+1)*2*CD + CD + tid];
            s2d+= (double)g_partf[(b2+2)*2*CD + tid];  q2 += (double)g_partf[(b2+2)*2*CD + CD + tid];
            s3 += (double)g_partf[(b2+3)*2*CD + tid];  q3 += (double)g_partf[(b2+3)*2*CD + CD + tid];
        }
        double s = (s0+s1)+(s2d+s3);
        double sq = (q0+q1)+(q2+q3);
        double m   = s / (double)CM;
        double var = sq / (double)CM - m*m;
        float rstd = rsqrtf((float)var + 1e-5f);
        float a = rstd * gam[tid];
        sa[tid] = a;
        sc[tid] = bet[tid] - (float)m * a;
    }
}

__global__ void __launch_bounds__(256)
xform_qkv_kernel(const float* __restrict__ Wq, const float* __restrict__ Wk,
                 const float* __restrict__ Wv,
                 const float* __restrict__ bq, const float* __restrict__ bk,
                 const float* __restrict__ bv,
                 const float* __restrict__ gam, const float* __restrict__ bet) {
    __shared__ float sa[CD], sc[CD];
    int tid = threadIdx.x;
    bn_finalize_smem(gam, bet, sa, sc, tid);
    __syncthreads();
    int nb = blockIdx.x * 64;
    {
        int n = nb + (tid & 63);
        int sel = n >> 7, ci = n & (CD-1);
        const float* W = (sel == 0) ? Wq : (sel == 1) ? Wk : Wv;
        for (int k = tid >> 6; k < CD; k += 4)
            g_wqkv[k*384 + n] = sa[k] * W[k*CD + ci];
    }
    if (tid < 64) {
        int n2 = nb + tid;
        int sel2 = n2 >> 7, ci2 = n2 & (CD-1);
        const float* W2 = (sel2 == 0) ? Wq : (sel2 == 1) ? Wk : Wv;
        const float* bb = (sel2 == 0) ? bq : (sel2 == 1) ? bk : bv;
        float s = 0.f;
        #pragma unroll 4
        for (int k = 0; k < CD; ++k) s += sc[k] * W2[k*CD + ci2];
        g_bqkv[n2] = bb[ci2] + s;
    }
}

__global__ void __launch_bounds__(256)
xform_l1_kernel(const float* __restrict__ W, const float* __restrict__ bias,
                const float* __restrict__ gam, const float* __restrict__ bet) {
    __shared__ float sa[CD], sc[CD];
    int tid = threadIdx.x;
    bn_finalize_smem(gam, bet, sa, sc, tid);
    __syncthreads();
    int nb = blockIdx.x * 64;
    {
        int n = nb + (tid & 63);
        for (int k = tid >> 6; k < CD; k += 4)
            g_wl1[k*(2*CD) + n] = sa[k] * W[k*(2*CD) + n];
    }
    if (tid < 64) {
        int n2 = nb + tid;
        float s = 0.f;
        #pragma unroll 4
        for (int k = 0; k < CD; ++k) s += sc[k] * W[k*(2*CD) + n2];
        g_bl1[n2] = bias[n2] + s;
    }
}

// ---------------- RoPE (layer 0 only) ---------------------------------------
__global__ void rope_kernel(float* __restrict__ qkv, const float* __restrict__ pos) {
    int idx = blockIdx.x * blockDim.x + threadIdx.x;
    if (idx >= CM * 64) return;
    int p = idx & 63;
    int t = idx >> 6;
    int group = p >> 5;
    int fidx  = p & 31;
    float freq = 3.14159265358979324f * (float)(fidx + 1);
    float ang = pos[t*2 + group] * freq;
    float sv, cv;
    sincosf(ang, &sv, &cv);
    int qb = t*3*CD + (p << 1);
    float q0 = qkv[qb], q1 = qkv[qb+1];
    qkv[qb]   = cv*q0 - sv*q1;
    qkv[qb+1] = cv*q1 + sv*q0;
    int kb = qb + CD;
    float k0 = qkv[kb], k1 = qkv[kb+1];
    qkv[kb]   = cv*k0 - sv*k1;
    qkv[kb+1] = cv*k1 + sv*k0;
}

// ---------------- tensor-core GEMM (3xTF32) ---------------------------------
#define AS_STR 36
#define BS_STR 72
#define SM_AHI 0
#define SM_ALO (128*AS_STR)
#define SM_BHI (2*128*AS_STR)
#define SM_BLO (2*128*AS_STR + 32*BS_STR)
#define GEMM_SMEM ((2*128*AS_STR + 2*32*BS_STR)*4)

__global__ void __launch_bounds__(256)
gemm_tc_kernel(const float* __restrict__ A, const float* __restrict__ W,
               const float* __restrict__ bias, const float* __restrict__ resid,
               float* __restrict__ C, int M, int K, int Nout, int relu, int mergeA) {
    extern __shared__ float sm[];
    float* As_hi = sm + SM_AHI;
    float* As_lo = sm + SM_ALO;
    float* Bs_hi = sm + SM_BHI;
    float* Bs_lo = sm + SM_BLO;

    int tid = threadIdx.x;
    int lane = tid & 31, warp = tid >> 5;
    int wm = warp & 3, wn = warp >> 2;
    int m_w = wm*32, n_w = wn*32;
    int g = lane >> 2, t = lane & 3;

    int bm0 = blockIdx.x * 128, bn0 = blockIdx.y * 64;

    float acc[2][4][4];
    #pragma unroll
    for (int i = 0; i < 2; ++i)
        #pragma unroll
        for (int j = 0; j < 4; ++j)
            #pragma unroll
            for (int u = 0; u < 4; ++u) acc[i][j][u] = 0.f;

    for (int k0 = 0; k0 < K; k0 += 32) {
        __syncthreads();
        #pragma unroll
        for (int it = 0; it < 4; ++it) {
            int f = tid + it*256;
            int row = f >> 3, c4 = (f & 7) << 2;
            float4 ga;
            if (mergeA) {
                int t_tok = bm0 + row;
                int kcol = k0 + c4;
                int head = kcol >> 5, d0 = kcol & 31;
                int i0 = t_tok*CH + head;
                float lsum = 0.f;
                float4 vs = make_float4(0.f, 0.f, 0.f, 0.f);
                #pragma unroll
                for (int sl2 = 0; sl2 < NSLICE; ++sl2) {
                    float4 v = *(const float4*)&g_pacc[((ull)sl2*CM*CH + i0)*32 + d0];
                    vs.x += v.x; vs.y += v.y; vs.z += v.z; vs.w += v.w;
                    lsum += g_pl[sl2*CM*CH + i0];
                }
                float f0 = 1.f / lsum;
                ga.x = vs.x*f0; ga.y = vs.y*f0; ga.z = vs.z*f0; ga.w = vs.w*f0;
            } else {
                ga = *(const float4*)&A[(bm0 + row)*K + k0 + c4];
            }
            float4 h4, l4;
            tf32split(ga.x, h4.x, l4.x);
            tf32split(ga.y, h4.y, l4.y);
            tf32split(ga.z, h4.z, l4.z);
            tf32split(ga.w, h4.w, l4.w);
            *(float4*)&As_hi[row*AS_STR + c4] = h4;
            *(float4*)&As_lo[row*AS_STR + c4] = l4;
        }
        #pragma unroll
        for (int it = 0; it < 2; ++it) {
            int f = tid + it*256;
            int row = f >> 4, c4 = (f & 15) << 2;
            float4 gb = *(const float4*)&W[(k0 + row)*Nout + bn0 + c4];
            float4 h4, l4;
            tf32split(gb.x, h4.x, l4.x);
            tf32split(gb.y, h4.y, l4.y);
            tf32split(gb.z, h4.z, l4.z);
            tf32split(gb.w, h4.w, l4.w);
            *(float4*)&Bs_hi[row*BS_STR + c4] = h4;
            *(float4*)&Bs_lo[row*BS_STR + c4] = l4;
        }
        __syncthreads();

        #pragma unroll
        for (int k8 = 0; k8 < 32; k8 += 8) {
            unsigned ah[2][4], al[2][4];
            #pragma unroll
            for (int mt = 0; mt < 2; ++mt) {
                int base = (m_w + mt*16 + g)*AS_STR + k8 + t;
                ah[mt][0] = __float_as_uint(As_hi[base]);
                ah[mt][1] = __float_as_uint(As_hi[base + 8*AS_STR]);
                ah[mt][2] = __float_as_uint(As_hi[base + 4]);
                ah[mt][3] = __float_as_uint(As_hi[base + 8*AS_STR + 4]);
                al[mt][0] = __float_as_uint(As_lo[base]);
                al[mt][1] = __float_as_uint(As_lo[base + 8*AS_STR]);
                al[mt][2] = __float_as_uint(As_lo[base + 4]);
                al[mt][3] = __float_as_uint(As_lo[base + 8*AS_STR + 4]);
            }
            unsigned bh[4][2], bl[4][2];
            #pragma unroll
            for (int nt = 0; nt < 4; ++nt) {
                int base = (k8 + t)*BS_STR + n_w + nt*8 + g;
                bh[nt][0] = __float_as_uint(Bs_hi[base]);
                bh[nt][1] = __float_as_uint(Bs_hi[base + 4*BS_STR]);
                bl[nt][0] = __float_as_uint(Bs_lo[base]);
                bl[nt][1] = __float_as_uint(Bs_lo[base + 4*BS_STR]);
            }
            #pragma unroll
            for (int mt = 0; mt < 2; ++mt)
                #pragma unroll
                for (int nt = 0; nt < 4; ++nt) {
                    mma_tf32(acc[mt][nt], al[mt], bh[nt]);
                    mma_tf32(acc[mt][nt], ah[mt], bl[nt]);
                    mma_tf32(acc[mt][nt], ah[mt], bh[nt]);
                }
        }
    }

    #pragma unroll
    for (int mt = 0; mt < 2; ++mt) {
        #pragma unroll
        for (int nt = 0; nt < 4; ++nt) {
            int row0 = bm0 + m_w + mt*16 + g;
            int col  = bn0 + n_w + nt*8 + 2*t;
            float2 bv = *(const float2*)&bias[col];
            float2 r0, r1;
            r0.x = acc[mt][nt][0] + bv.x;  r0.y = acc[mt][nt][1] + bv.y;
            r1.x = acc[mt][nt][2] + bv.x;  r1.y = acc[mt][nt][3] + bv.y;
            if (resid) {
                float2 v0 = *(const float2*)&resid[row0*Nout + col];
                float2 v1 = *(const float2*)&resid[(row0+8)*Nout + col];
                r0.x += v0.x; r0.y += v0.y;
                r1.x += v1.x; r1.y += v1.y;
            }
            if (relu) {
                r0.x = fmaxf(r0.x, 0.f); r0.y = fmaxf(r0.y, 0.f);
                r1.x = fmaxf(r1.x, 0.f); r1.y = fmaxf(r1.y, 0.f);
            }
            *(float2*)&C[row0*Nout + col]     = r0;
            *(float2*)&C[(row0+8)*Nout + col] = r1;
        }
    }
}

// ---------------- attention: 128 threads, warp-pair j-split (R13 shape) -----
// grid (NC2, 4 qtiles, CB*2 jhalf); 128 threads = 2 jparts x (16 slots x 4 heads).
#define TJR 16
#define KS_OFF 0
#define VS_OFF (2*TJR*128)
#define PS_OFF (4*TJR*128)
#define SS_OFF (4*TJR*128 + 2*2*TJR)
#define ATTN_SMEM ((4*TJR*128 + 2*2*TJR + 2*TJR)*4)

__global__ void __launch_bounds__(128)
attn_kernel(const float* __restrict__ qkv, const float* __restrict__ pos,
            const float* __restrict__ sqv) {
    extern __shared__ float smn[];

    int cell = blockIdx.x, qt = blockIdx.y;
    int b = blockIdx.z >> 1, jh = blockIdx.z & 1;
    int cidx = b*NC2 + cell;
    int cstart = g_cstart[b][cell];
    int ccount = g_cstart[b][cell+1] - cstart;
    if (qt*16 >= ccount) return;

    int ncand = g_ncand[cidx];          // multiple of 32
    int cbase = cidx*CAND_CAP;
    const int* cand = &g_cand[cbase];
    int nt32 = ncand >> 5;
    int h32 = (nt32 + 1) >> 1;
    int jstart = jh ? h32*32 : 0;
    int jend   = jh ? ncand : h32*32;

    int tid  = threadIdx.x;
    int w    = tid >> 5, lane = tid & 31;
    int jpart = w >> 1;                       // 0: rows 0-7, 1: rows 8-15
    int slot = lane & 15;
    int head = ((w & 1) << 1) | (lane >> 4);
    int slice = jh*2 + jpart;

    if (jstart >= jend) {               // empty half: write zero partials
        for (int q0 = qt*16; q0 < ccount; q0 += 64) {
            if ((q0 + slot) < ccount) {
                int qi = g_ord[b][cstart + q0 + slot];
                int t = b*CN + qi;
                int pidx = (slice*CM + t)*CH + head;
                g_pl[pidx] = 0.f;
                ulonglong2* ap = (ulonglong2*)&g_pacc[(ull)pidx*32];
                ulonglong2 z; z.x = 0ull; z.y = 0ull;
                #pragma unroll
                for (int u = 0; u < 8; ++u) ap[u] = z;
            }
        }
        return;
    }
    int ntiles = (jend - jstart + TJR - 1) / TJR;

    unsigned sb = smem_u32(smn);

    // scale folded with log2(e): softmax exp(s) = exp2(s * log2e)
    const float scale = 0.17677669529663687f * 1.4426950408889634f;
    const float R2 = 0.0625f;
    ull scale2 = fpack2(scale, scale);

    for (int q0 = qt*16; q0 < ccount; q0 += 64) {
        bool active = (q0 + slot) < ccount;
        int qidx = active ? (q0 + slot) : 0;
        int qi = g_ord[b][cstart + qidx];
        int t = b*CN + qi;

        ull qr2[16];
        const ulonglong2* qp = (const ulonglong2*)&qkv[t*3*CD + head*CHD];
        #pragma unroll
        for (int u = 0; u < 8; ++u) {
            ulonglong2 qq = qp[u];
            qr2[2*u]   = fmul2(qq.x, scale2);
            qr2[2*u+1] = fmul2(qq.y, scale2);
        }
        float2 pi  = ((const float2*)pos)[t];
        float  sqi = sqv[t];

        float l = 0.f;
        ull acc2[16];
        #pragma unroll
        for (int u = 0; u < 16; ++u) acc2[u] = 0ull;

        // prologue: stage tile 0 (4 warps x 4 rows)
        {
            int ts = jstart;
            #pragma unroll
            for (int rr = 0; rr < TJR/4; ++rr) {
                int r = w + rr*4;
                int tj = b*CN + cand[ts + r];
                const char* gk = (const char*)&qkv[tj*3*CD + CD];
                const char* gv = (const char*)&qkv[tj*3*CD + 2*CD];
                cp16(sb + (KS_OFF + r*128)*4 + lane*16, gk + lane*16);
                cp16(sb + (VS_OFF + r*128)*4 + lane*16, gv + lane*16);
            }
            if (tid < TJR) {
                cp8(sb + (PS_OFF + tid*2)*4, &g_cpos[cbase + ts + tid]);
                cp4(sb + (SS_OFF + tid)*4,   &g_csq [cbase + ts + tid]);
            }
            asm volatile("cp.async.commit_group;" ::: "memory");
        }

        for (int tl = 0; tl < ntiles; ++tl) {
            int cur = tl & 1;
            if (tl + 1 < ntiles) {
                int nb2 = (tl + 1) & 1;
                int ts = jstart + (tl+1)*TJR;
                #pragma unroll
                for (int rr = 0; rr < TJR/4; ++rr) {
                    int r = w + rr*4;
                    int tj = b*CN + cand[ts + r];
                    const char* gk = (const char*)&qkv[tj*3*CD + CD];
                    const char* gv = (const char*)&qkv[tj*3*CD + 2*CD];
                    cp16(sb + (KS_OFF + nb2*TJR*128 + r*128)*4 + lane*16, gk + lane*16);
                    cp16(sb + (VS_OFF + nb2*TJR*128 + r*128)*4 + lane*16, gv + lane*16);
                }
                if (tid < TJR) {
                    cp8(sb + (PS_OFF + nb2*2*TJR + tid*2)*4, &g_cpos[cbase + ts + tid]);
                    cp4(sb + (SS_OFF + nb2*TJR + tid)*4,     &g_csq [cbase + ts + tid]);
                }
                asm volatile("cp.async.commit_group;" ::: "memory");
                asm volatile("cp.async.wait_group 1;" ::: "memory");
            } else {
                asm volatile("cp.async.wait_group 0;" ::: "memory");
            }
            __syncthreads();

            const float*  Kb = smn + KS_OFF + cur*TJR*128;
            const float*  Vb = smn + VS_OFF + cur*TJR*128;
            const float2* Pb = (const float2*)(smn + PS_OFF + cur*2*TJR);
            const float*  Sb = smn + SS_OFF + cur*TJR;

            #pragma unroll
            for (int j0j = 0; j0j < TJR/2; ++j0j) {
                int j = jpart*(TJR/2) + j0j;
                float2 pj = Pb[j];
                float d2 = sqi + Sb[j] - 2.f*(pi.x*pj.x + pi.y*pj.y);
                bool inw = (d2 <= R2);

                const ulonglong2* kr = (const ulonglong2*)&Kb[j*128 + (head<<5)];
                ulonglong2 k0v = kr[0], k1v = kr[1], k2v = kr[2], k3v = kr[3];
                ull sa  = fmul2(qr2[0],  k0v.x);
                ull sb2 = fmul2(qr2[1],  k0v.y);
                ull sc2 = fmul2(qr2[2],  k1v.x);
                ull sd  = fmul2(qr2[3],  k1v.y);
                sa  = ffma2(qr2[4],  k2v.x, sa);
                sb2 = ffma2(qr2[5],  k2v.y, sb2);
                sc2 = ffma2(qr2[6],  k3v.x, sc2);
                sd  = ffma2(qr2[7],  k3v.y, sd);
                ulonglong2 k4v = kr[4], k5v = kr[5], k6v = kr[6], k7v = kr[7];
                sa  = ffma2(qr2[8],  k4v.x, sa);
                sb2 = ffma2(qr2[9],  k4v.y, sb2);
                sc2 = ffma2(qr2[10], k5v.x, sc2);
                sd  = ffma2(qr2[11], k5v.y, sd);
                sa  = ffma2(qr2[12], k6v.x, sa);
                sb2 = ffma2(qr2[13], k6v.y, sb2);
                sc2 = ffma2(qr2[14], k7v.x, sc2);
                sd  = ffma2(qr2[15], k7v.y, sd);
                float sl, sh;
                funpack2(fadd2(fadd2(sa, sb2), fadd2(sc2, sd)), sl, sh);
                float s = sl + sh;

                float pb = inw ? exp2f(s) : 0.f;
                l += pb;
                ull pb2 = fpack2(pb, pb);
                const ulonglong2* vr = (const ulonglong2*)&Vb[j*128 + (head<<5)];
                #pragma unroll
                for (int u = 0; u < 8; ++u) {
                    ulonglong2 vv = vr[u];
                    acc2[2*u]   = ffma2(pb2, vv.x, acc2[2*u]);
                    acc2[2*u+1] = ffma2(pb2, vv.y, acc2[2*u+1]);
                }
            }
            __syncthreads();
        }

        if (active) {
            int pidx = (slice*CM + t)*CH + head;
            g_pl[pidx] = l;
            ulonglong2* ap = (ulonglong2*)&g_pacc[(ull)pidx*32];
            #pragma unroll
            for (int u = 0; u < 8; ++u) {
                ulonglong2 wv; wv.x = acc2[2*u]; wv.y = acc2[2*u+1];
                ap[u] = wv;
            }
        }
    }
}

// ---------------- launch ----------------------------------------------------
extern "C" void kernel_launch(void* const* d_in, const int* in_sizes, int n_in,
                              void* d_out, int out_size) {
    const float* x    = (const float*)d_in[0];
    const float* pos  = (const float*)d_in[1];
    const float* Wq_w = (const float*)d_in[2];
    const float* Wq_b = (const float*)d_in[3];
    const float* Wk_w = (const float*)d_in[4];
    const float* Wk_b = (const float*)d_in[5];
    const float* Wv_w = (const float*)d_in[6];
    const float* Wv_b = (const float*)d_in[7];
    const float* Wo_w = (const float*)d_in[8];
    const float* Wo_b = (const float*)d_in[9];
    const float* n1_g = (const float*)d_in[10];
    const float* n1_b = (const float*)d_in[11];
    const float* n2_g = (const float*)d_in[12];
    const float* n2_b = (const float*)d_in[13];
    const float* l1_w = (const float*)d_in[14];
    const float* l1_b = (const float*)d_in[15];
    const float* l2_w = (const float*)d_in[16];
    const float* l2_b = (const float*)d_in[17];
    float* out = (float*)d_out;

    float *gx, *gqkv, *ghid, *gwqkv, *gbqkv, *gwl1, *gbl1, *gsq, *gpartf;
    cudaGetSymbolAddress((void**)&gx,    g_x);
    cudaGetSymbolAddress((void**)&gqkv,  g_qkv);
    cudaGetSymbolAddress((void**)&ghid,  g_hid);
    cudaGetSymbolAddress((void**)&gpartf,g_partf);
    cudaGetSymbolAddress((void**)&gwqkv, g_wqkv);
    cudaGetSymbolAddress((void**)&gbqkv, g_bqkv);
    cudaGetSymbolAddress((void**)&gwl1,  g_wl1);
    cudaGetSymbolAddress((void**)&gbl1,  g_bl1);
    cudaGetSymbolAddress((void**)&gsq,   g_sq);

    cudaFuncSetAttribute(gemm_tc_kernel,
                         cudaFuncAttributeMaxDynamicSharedMemorySize, GEMM_SMEM);
    cudaFuncSetAttribute(attn_kernel,
                         cudaFuncAttributeMaxDynamicSharedMemorySize, ATTN_SMEM);

    dim3 gP(CM/128, CD/64);
    dim3 gQKV(CM/128, 3*CD/64);
    dim3 gF(CM/128, 2*CD/64);

    copy_kernel<<<(CM*CD + 255)/256, 256>>>(x, gx, CM*CD);
    bin_kernel<<<1, 1024>>>(pos);
    build_cands_kernel<<<CB*NC2/4, 128>>>(pos);

    for (int i = 0; i < 2; ++i) {
        const float* xin = (i == 0) ? x : gx;

        // --- attention block (BN folded into QKV weights) ---
        bn_stats_kernel<<<NPART, 128>>>(xin, gpartf);
        xform_qkv_kernel<<<6, 256>>>(Wq_w + i*CD*CD, Wk_w + i*CD*CD, Wv_w + i*CD*CD,
                                     Wq_b + i*CD, Wk_b + i*CD, Wv_b + i*CD,
                                     n1_g + i*CD, n1_b + i*CD);
        gemm_tc_kernel<<<gQKV, 256, GEMM_SMEM>>>(xin, gwqkv, gbqkv, nullptr, gqkv,
                                                 CM, CD, 3*CD, 0, 0);
        if (i == 0)
            rope_kernel<<<(CM*64 + 255)/256, 256>>>(gqkv, pos);

        attn_kernel<<<dim3(NC2, 4, CB*2), 128, ATTN_SMEM>>>(gqkv, pos, gsq);
        gemm_tc_kernel<<<gP, 256, GEMM_SMEM>>>(nullptr, Wo_w + i*CD*CD, Wo_b + i*CD,
                                               gx, gx, CM, CD, CD, 0, 1);

        // --- FFN block (BN folded into l1 weights) ---
        bn_stats_kernel<<<NPART, 128>>>(gx, gpartf);
        xform_l1_kernel<<<4, 256>>>(l1_w + i*CD*2*CD, l1_b + i*2*CD,
                                    n2_g + i*CD, n2_b + i*CD);
        gemm_tc_kernel<<<gF, 256, GEMM_SMEM>>>(gx, gwl1, gbl1, nullptr, ghid,
                                               CM, CD, 2*CD, 1, 0);
        float* dst = (i == 1) ? out : gx;
        gemm_tc_kernel<<<gP, 256, GEMM_SMEM>>>(ghid, l2_w + i*2*CD*CD, l2_b + i*CD,
                                               gx, dst, CM, 2*CD, CD, 0, 0);
    }
}

// round 16
// speedup vs baseline: 1.0239x; 1.0030x over previous
#include <cuda_runtime.h>
#include <math_constants.h>

#define CB 2
#define CN 4096
#define CD 128
#define CH 4
#define CHD 32
#define CM (CB*CN)   // 8192 tokens
#define NCELL 16
#define NC2 (NCELL*NCELL)
#define CAND_CAP 2048
#define NPART 256    // bn_stats partial blocks
#define NSLICE 4     // attention partial slices: 2 j-halves x 2 jparts

typedef unsigned long long ull;

// ---------------- f32x2 packed helpers (sm_100+ PTX) -----------------------
__device__ __forceinline__ ull ffma2(ull a, ull b, ull c) {
    ull d; asm("fma.rn.f32x2 %0,%1,%2,%3;" : "=l"(d) : "l"(a), "l"(b), "l"(c)); return d;
}
__device__ __forceinline__ ull fmul2(ull a, ull b) {
    ull d; asm("mul.rn.f32x2 %0,%1,%2;" : "=l"(d) : "l"(a), "l"(b)); return d;
}
__device__ __forceinline__ ull fadd2(ull a, ull b) {
    ull d; asm("add.rn.f32x2 %0,%1,%2;" : "=l"(d) : "l"(a), "l"(b)); return d;
}
__device__ __forceinline__ ull fpack2(float lo, float hi) {
    ull d; asm("mov.b64 %0,{%1,%2};" : "=l"(d) : "f"(lo), "f"(hi)); return d;
}
__device__ __forceinline__ void funpack2(ull a, float& lo, float& hi) {
    asm("mov.b64 {%0,%1},%2;" : "=f"(lo), "=f"(hi) : "l"(a));
}

// ---------------- cp.async helpers ------------------------------------------
__device__ __forceinline__ unsigned smem_u32(const void* p) {
    unsigned a;
    asm("{ .reg .u64 t; cvta.to.shared.u64 t, %1; cvt.u32.u64 %0, t; }" : "=r"(a) : "l"(p));
    return a;
}
__device__ __forceinline__ void cp16(unsigned s, const void* g) {
    asm volatile("cp.async.cg.shared.global [%0], [%1], 16;" :: "r"(s), "l"(g));
}
__device__ __forceinline__ void cp8(unsigned s, const void* g) {
    asm volatile("cp.async.ca.shared.global [%0], [%1], 8;" :: "r"(s), "l"(g));
}
__device__ __forceinline__ void cp4(unsigned s, const void* g) {
    asm volatile("cp.async.ca.shared.global [%0], [%1], 4;" :: "r"(s), "l"(g));
}

// ---------------- tf32 split helpers ----------------------------------------
__device__ __forceinline__ void tf32split(float x, float& hi, float& lo) {
    unsigned h;
    asm("cvt.rna.tf32.f32 %0, %1;" : "=r"(h) : "f"(x));
    float hf = __uint_as_float(h);
    float l = x - hf;
    unsigned lb;
    asm("cvt.rna.tf32.f32 %0, %1;" : "=r"(lb) : "f"(l));
    hi = hf; lo = __uint_as_float(lb);
}

__device__ __forceinline__ void mma_tf32(float* c, const unsigned* a, const unsigned* b) {
    asm volatile(
        "mma.sync.aligned.m16n8k8.row.col.f32.tf32.tf32.f32 "
        "{%0,%1,%2,%3},{%4,%5,%6,%7},{%8,%9},{%0,%1,%2,%3};\n"
        : "+f"(c[0]), "+f"(c[1]), "+f"(c[2]), "+f"(c[3])
        : "r"(a[0]), "r"(a[1]), "r"(a[2]), "r"(a[3]), "r"(b[0]), "r"(b[1]));
}

// ---------------- scratch ---------------------------------------------------
__device__ float  g_x   [CM*CD];
__device__ float  g_qkv [CM*3*CD];
__device__ float  g_hid [CM*2*CD];
__device__ float  g_partf[NPART*2*CD];
__device__ float  g_sq  [CM];
__device__ float  g_wqkv[CD*3*CD];
__device__ float  g_bqkv[3*CD];
__device__ float  g_wl1 [CD*2*CD];
__device__ float  g_bl1 [2*CD];
__device__ int    g_cstart[CB][NC2+1];
__device__ int    g_ord   [CB][CN];
__device__ int    g_cand  [CB*NC2*CAND_CAP];
__device__ float2 g_cpos  [CB*NC2*CAND_CAP];
__device__ float  g_csq   [CB*NC2*CAND_CAP];
__device__ int    g_ncand [CB*NC2];
// attention partials: [slice][token][head]
__device__ float g_pl  [NSLICE*CM*CH];
__device__ float g_pacc[NSLICE*CM*CH*32];

// ---------------- fused binning: hist + scan + scatter (one block) ----------
__global__ void __launch_bounds__(1024)
bin_kernel(const float* __restrict__ pos) {
    __shared__ int scnt[CB*NC2];
    __shared__ int scur[CB*NC2];
    int tid = threadIdx.x;
    if (tid < CB*NC2) scnt[tid] = 0;
    __syncthreads();
    int mycell[8], mytok[8];
    #pragma unroll
    for (int i = 0; i < 8; ++i) {
        int t = tid + i*1024;
        int b = t >> 12, n = t & (CN-1);
        float px = pos[2*t], py = pos[2*t+1];
        int cx = min(NCELL-1, max(0, (int)(px * NCELL)));
        int cy = min(NCELL-1, max(0, (int)(py * NCELL)));
        int c = cy*NCELL + cx;
        g_sq[t] = px*px + py*py;
        mycell[i] = b*NC2 + c;
        mytok[i]  = n;
        atomicAdd(&scnt[b*NC2 + c], 1);
    }
    __syncthreads();
    int v = (tid < CB*NC2) ? scnt[tid] : 0;
    for (int off = 1; off < NC2; off <<= 1) {
        int t2 = 0;
        if (tid < CB*NC2 && (tid & (NC2-1)) >= off) t2 = scnt[tid-off];
        __syncthreads();
        if (tid < CB*NC2) scnt[tid] += t2;
        __syncthreads();
    }
    if (tid < CB*NC2) {
        int incl = scnt[tid];
        int excl = incl - v;
        int b = tid >> 8, c = tid & (NC2-1);
        g_cstart[b][c] = excl;
        scur[tid] = excl;
        if (c == NC2-1) g_cstart[b][NC2] = incl;
    }
    __syncthreads();
    #pragma unroll
    for (int i = 0; i < 8; ++i) {
        int r = atomicAdd(&scur[mycell[i]], 1);
        int b = mycell[i] >> 8;
        g_ord[b][r] = mytok[i];
    }
}

// ---------------- candidate list build: one warp per (b,cell) ---------------
__global__ void __launch_bounds__(128)
build_cands_kernel(const float* __restrict__ pos) {
    int wid = threadIdx.x >> 5, lane = threadIdx.x & 31;
    int cidx = blockIdx.x * 4 + wid;
    int b = cidx >> 8, cell = cidx & (NC2-1);
    int cx = cell & (NCELL-1), cy = cell >> 4;
    float X0 = cx * (1.f/NCELL), X1 = (cx+1) * (1.f/NCELL);
    float Y0 = cy * (1.f/NCELL), Y1 = (cy+1) * (1.f/NCELL);
    const float R2m = 0.0625f + 1e-4f;
    int base = cidx * CAND_CAP;
    int* dst = &g_cand[base];
    int cnt = 0;
    for (int dy = -5; dy <= 5; ++dy) {
        int yy = cy + dy;
        if (yy < 0 || yy >= NCELL) continue;
        int bb = abs(dy) > 1 ? abs(dy) - 1 : 0;
        int rem = 16 - bb*bb;
        if (rem < 0) continue;
        int kx = (int)floorf(sqrtf((float)rem)) + 1;
        int x0 = cx - kx; if (x0 < 0) x0 = 0;
        int x1 = cx + kx; if (x1 > NCELL-1) x1 = NCELL-1;
        int S = g_cstart[b][yy*NCELL + x0];
        int E = g_cstart[b][yy*NCELL + x1 + 1];
        for (int j0 = S; j0 < E; j0 += 32) {
            int src = j0 + lane;
            bool keep = false; int tok = 0; float2 p = make_float2(0.f, 0.f);
            if (src < E) {
                tok = g_ord[b][src];
                p = ((const float2*)pos)[b*CN + tok];
                float ddx = fmaxf(fmaxf(X0 - p.x, p.x - X1), 0.f);
                float ddy = fmaxf(fmaxf(Y0 - p.y, p.y - Y1), 0.f);
                keep = (ddx*ddx + ddy*ddy) <= R2m;
            }
            unsigned bal = __ballot_sync(0xFFFFFFFFu, keep);
            int ofs = __popc(bal & ((1u << lane) - 1));
            if (keep && cnt + ofs < CAND_CAP) {
                int w = cnt + ofs;
                dst[w] = tok;
                g_cpos[base + w] = p;
                g_csq[base + w] = p.x*p.x + p.y*p.y;
            }
            cnt += __popc(bal);
        }
    }
    if (cnt > CAND_CAP) cnt = CAND_CAP;
    int padded = (cnt + 31) & ~31;
    if (padded > CAND_CAP) padded = CAND_CAP;
    for (int i2 = cnt + lane; i2 < padded; i2 += 32) {
        dst[i2] = 0;
        g_cpos[base + i2] = make_float2(0.f, 0.f);
        g_csq[base + i2] = CUDART_INF_F;
    }
    if (lane == 0) g_ncand[cidx] = padded;
}

// ---------------- BatchNorm stats (fp32 partials, wide grid) -----------------
__global__ void __launch_bounds__(128)
bn_stats_kernel(const float* __restrict__ x, float* __restrict__ part) {
    int d = threadIdx.x;
    int blk = blockIdx.x;
    int r0 = blk * (CM / NPART);
    float s = 0.f, s2 = 0.f;
    #pragma unroll 8
    for (int r = 0; r < CM/NPART; ++r) {
        float v = x[(r0 + r)*CD + d];
        s  += v;
        s2 += v*v;
    }
    part[blk*2*CD + d]      = s;
    part[blk*2*CD + CD + d] = s2;
}

// ---------------- BN-folded weight transforms -------------------------------
__device__ __forceinline__ void bn_finalize_smem(const float* gam, const float* bet,
                                                 float* sa, float* sc, int tid) {
    if (tid < CD) {
        double s0=0,s1=0,s2d=0,s3=0,q0=0,q1=0,q2=0,q3=0;
        #pragma unroll 4
        for (int b2 = 0; b2 < NPART; b2 += 4) {
            s0 += (double)g_partf[(b2+0)*2*CD + tid];  q0 += (double)g_partf[(b2+0)*2*CD + CD + tid];
            s1 += (double)g_partf[(b2+1)*2*CD + tid];  q1 += (double)g_partf[(b2+1)*2*CD + CD + tid];
            s2d+= (double)g_partf[(b2+2)*2*CD + tid];  q2 += (double)g_partf[(b2+2)*2*CD + CD + tid];
            s3 += (double)g_partf[(b2+3)*2*CD + tid];  q3 += (double)g_partf[(b2+3)*2*CD + CD + tid];
        }
        double s = (s0+s1)+(s2d+s3);
        double sq = (q0+q1)+(q2+q3);
        double m   = s / (double)CM;
        double var = sq / (double)CM - m*m;
        float rstd = rsqrtf((float)var + 1e-5f);
        float a = rstd * gam[tid];
        sa[tid] = a;
        sc[tid] = bet[tid] - (float)m * a;
    }
}

__global__ void __launch_bounds__(256)
xform_qkv_kernel(const float* __restrict__ Wq, const float* __restrict__ Wk,
                 const float* __restrict__ Wv,
                 const float* __restrict__ bq, const float* __restrict__ bk,
                 const float* __restrict__ bv,
                 const float* __restrict__ gam, const float* __restrict__ bet) {
    __shared__ float sa[CD], sc[CD];
    int tid = threadIdx.x;
    bn_finalize_smem(gam, bet, sa, sc, tid);
    __syncthreads();
    int nb = blockIdx.x * 64;
    {
        int n = nb + (tid & 63);
        int sel = n >> 7, ci = n & (CD-1);
        const float* W = (sel == 0) ? Wq : (sel == 1) ? Wk : Wv;
        for (int k = tid >> 6; k < CD; k += 4)
            g_wqkv[k*384 + n] = sa[k] * W[k*CD + ci];
    }
    if (tid < 64) {
        int n2 = nb + tid;
        int sel2 = n2 >> 7, ci2 = n2 & (CD-1);
        const float* W2 = (sel2 == 0) ? Wq : (sel2 == 1) ? Wk : Wv;
        const float* bb = (sel2 == 0) ? bq : (sel2 == 1) ? bk : bv;
        float s = 0.f;
        #pragma unroll 4
        for (int k = 0; k < CD; ++k) s += sc[k] * W2[k*CD + ci2];
        g_bqkv[n2] = bb[ci2] + s;
    }
}

__global__ void __launch_bounds__(256)
xform_l1_kernel(const float* __restrict__ W, const float* __restrict__ bias,
                const float* __restrict__ gam, const float* __restrict__ bet) {
    __shared__ float sa[CD], sc[CD];
    int tid = threadIdx.x;
    bn_finalize_smem(gam, bet, sa, sc, tid);
    __syncthreads();
    int nb = blockIdx.x * 64;
    {
        int n = nb + (tid & 63);
        for (int k = tid >> 6; k < CD; k += 4)
            g_wl1[k*(2*CD) + n] = sa[k] * W[k*(2*CD) + n];
    }
    if (tid < 64) {
        int n2 = nb + tid;
        float s = 0.f;
        #pragma unroll 4
        for (int k = 0; k < CD; ++k) s += sc[k] * W[k*(2*CD) + n2];
        g_bl1[n2] = bias[n2] + s;
    }
}

// ---------------- RoPE (layer 0 only) ---------------------------------------
__global__ void rope_kernel(float* __restrict__ qkv, const float* __restrict__ pos) {
    int idx = blockIdx.x * blockDim.x + threadIdx.x;
    if (idx >= CM * 64) return;
    int p = idx & 63;
    int t = idx >> 6;
    int group = p >> 5;
    int fidx  = p & 31;
    float freq = 3.14159265358979324f * (float)(fidx + 1);
    float ang = pos[t*2 + group] * freq;
    float sv, cv;
    sincosf(ang, &sv, &cv);
    int qb = t*3*CD + (p << 1);
    float q0 = qkv[qb], q1 = qkv[qb+1];
    qkv[qb]   = cv*q0 - sv*q1;
    qkv[qb+1] = cv*q1 + sv*q0;
    int kb = qb + CD;
    float k0 = qkv[kb], k1 = qkv[kb+1];
    qkv[kb]   = cv*k0 - sv*k1;
    qkv[kb+1] = cv*k1 + sv*k0;
}

// ---------------- tensor-core GEMM (3xTF32) ---------------------------------
#define AS_STR 36
#define BS_STR 72
#define SM_AHI 0
#define SM_ALO (128*AS_STR)
#define SM_BHI (2*128*AS_STR)
#define SM_BLO (2*128*AS_STR + 32*BS_STR)
#define GEMM_SMEM ((2*128*AS_STR + 2*32*BS_STR)*4)

__global__ void __launch_bounds__(256)
gemm_tc_kernel(const float* __restrict__ A, const float* __restrict__ W,
               const float* __restrict__ bias, const float* __restrict__ resid,
               float* __restrict__ C, int M, int K, int Nout, int relu, int mergeA) {
    extern __shared__ float sm[];
    float* As_hi = sm + SM_AHI;
    float* As_lo = sm + SM_ALO;
    float* Bs_hi = sm + SM_BHI;
    float* Bs_lo = sm + SM_BLO;

    int tid = threadIdx.x;
    int lane = tid & 31, warp = tid >> 5;
    int wm = warp & 3, wn = warp >> 2;
    int m_w = wm*32, n_w = wn*32;
    int g = lane >> 2, t = lane & 3;

    int bm0 = blockIdx.x * 128, bn0 = blockIdx.y * 64;

    float acc[2][4][4];
    #pragma unroll
    for (int i = 0; i < 2; ++i)
        #pragma unroll
        for (int j = 0; j < 4; ++j)
            #pragma unroll
            for (int u = 0; u < 4; ++u) acc[i][j][u] = 0.f;

    for (int k0 = 0; k0 < K; k0 += 32) {
        __syncthreads();
        #pragma unroll
        for (int it = 0; it < 4; ++it) {
            int f = tid + it*256;
            int row = f >> 3, c4 = (f & 7) << 2;
            float4 ga;
            if (mergeA) {
                int t_tok = bm0 + row;
                int kcol = k0 + c4;
                int head = kcol >> 5, d0 = kcol & 31;
                int i0 = t_tok*CH + head;
                float lsum = 0.f;
                float4 vs = make_float4(0.f, 0.f, 0.f, 0.f);
                #pragma unroll
                for (int sl2 = 0; sl2 < NSLICE; ++sl2) {
                    float4 v = *(const float4*)&g_pacc[((ull)sl2*CM*CH + i0)*32 + d0];
                    vs.x += v.x; vs.y += v.y; vs.z += v.z; vs.w += v.w;
                    lsum += g_pl[sl2*CM*CH + i0];
                }
                float f0 = 1.f / lsum;
                ga.x = vs.x*f0; ga.y = vs.y*f0; ga.z = vs.z*f0; ga.w = vs.w*f0;
            } else {
                ga = *(const float4*)&A[(bm0 + row)*K + k0 + c4];
            }
            float4 h4, l4;
            tf32split(ga.x, h4.x, l4.x);
            tf32split(ga.y, h4.y, l4.y);
            tf32split(ga.z, h4.z, l4.z);
            tf32split(ga.w, h4.w, l4.w);
            *(float4*)&As_hi[row*AS_STR + c4] = h4;
            *(float4*)&As_lo[row*AS_STR + c4] = l4;
        }
        #pragma unroll
        for (int it = 0; it < 2; ++it) {
            int f = tid + it*256;
            int row = f >> 4, c4 = (f & 15) << 2;
            float4 gb = *(const float4*)&W[(k0 + row)*Nout + bn0 + c4];
            float4 h4, l4;
            tf32split(gb.x, h4.x, l4.x);
            tf32split(gb.y, h4.y, l4.y);
            tf32split(gb.z, h4.z, l4.z);
            tf32split(gb.w, h4.w, l4.w);
            *(float4*)&Bs_hi[row*BS_STR + c4] = h4;
            *(float4*)&Bs_lo[row*BS_STR + c4] = l4;
        }
        __syncthreads();

        #pragma unroll
        for (int k8 = 0; k8 < 32; k8 += 8) {
            unsigned ah[2][4], al[2][4];
            #pragma unroll
            for (int mt = 0; mt < 2; ++mt) {
                int base = (m_w + mt*16 + g)*AS_STR + k8 + t;
                ah[mt][0] = __float_as_uint(As_hi[base]);
                ah[mt][1] = __float_as_uint(As_hi[base + 8*AS_STR]);
                ah[mt][2] = __float_as_uint(As_hi[base + 4]);
                ah[mt][3] = __float_as_uint(As_hi[base + 8*AS_STR + 4]);
                al[mt][0] = __float_as_uint(As_lo[base]);
                al[mt][1] = __float_as_uint(As_lo[base + 8*AS_STR]);
                al[mt][2] = __float_as_uint(As_lo[base + 4]);
                al[mt][3] = __float_as_uint(As_lo[base + 8*AS_STR + 4]);
            }
            unsigned bh[4][2], bl[4][2];
            #pragma unroll
            for (int nt = 0; nt < 4; ++nt) {
                int base = (k8 + t)*BS_STR + n_w + nt*8 + g;
                bh[nt][0] = __float_as_uint(Bs_hi[base]);
                bh[nt][1] = __float_as_uint(Bs_hi[base + 4*BS_STR]);
                bl[nt][0] = __float_as_uint(Bs_lo[base]);
                bl[nt][1] = __float_as_uint(Bs_lo[base + 4*BS_STR]);
            }
            #pragma unroll
            for (int mt = 0; mt < 2; ++mt)
                #pragma unroll
                for (int nt = 0; nt < 4; ++nt) {
                    mma_tf32(acc[mt][nt], al[mt], bh[nt]);
                    mma_tf32(acc[mt][nt], ah[mt], bl[nt]);
                    mma_tf32(acc[mt][nt], ah[mt], bh[nt]);
                }
        }
    }

    #pragma unroll
    for (int mt = 0; mt < 2; ++mt) {
        #pragma unroll
        for (int nt = 0; nt < 4; ++nt) {
            int row0 = bm0 + m_w + mt*16 + g;
            int col  = bn0 + n_w + nt*8 + 2*t;
            float2 bv = *(const float2*)&bias[col];
            float2 r0, r1;
            r0.x = acc[mt][nt][0] + bv.x;  r0.y = acc[mt][nt][1] + bv.y;
            r1.x = acc[mt][nt][2] + bv.x;  r1.y = acc[mt][nt][3] + bv.y;
            if (resid) {
                float2 v0 = *(const float2*)&resid[row0*Nout + col];
                float2 v1 = *(const float2*)&resid[(row0+8)*Nout + col];
                r0.x += v0.x; r0.y += v0.y;
                r1.x += v1.x; r1.y += v1.y;
            }
            if (relu) {
                r0.x = fmaxf(r0.x, 0.f); r0.y = fmaxf(r0.y, 0.f);
                r1.x = fmaxf(r1.x, 0.f); r1.y = fmaxf(r1.y, 0.f);
            }
            *(float2*)&C[row0*Nout + col]     = r0;
            *(float2*)&C[(row0+8)*Nout + col] = r1;
        }
    }
}

// ---------------- attention: 128 threads, warp-pair j-split -----------------
// grid (NC2, 2 qtiles, CB*2 jhalf); 128 threads = 2 jparts x (16 slots x 4 heads).
#define TJR 16
#define KS_OFF 0
#define VS_OFF (2*TJR*128)
#define PS_OFF (4*TJR*128)
#define SS_OFF (4*TJR*128 + 2*2*TJR)
#define ATTN_SMEM ((4*TJR*128 + 2*2*TJR + 2*TJR)*4)

__global__ void __launch_bounds__(128)
attn_kernel(const float* __restrict__ qkv, const float* __restrict__ pos,
            const float* __restrict__ sqv) {
    extern __shared__ float smn[];

    int cell = blockIdx.x, qt = blockIdx.y;
    int b = blockIdx.z >> 1, jh = blockIdx.z & 1;
    int cidx = b*NC2 + cell;
    int cstart = g_cstart[b][cell];
    int ccount = g_cstart[b][cell+1] - cstart;
    if (qt*16 >= ccount) return;

    int ncand = g_ncand[cidx];          // multiple of 32
    int cbase = cidx*CAND_CAP;
    const int* cand = &g_cand[cbase];
    int nt32 = ncand >> 5;
    int h32 = (nt32 + 1) >> 1;
    int jstart = jh ? h32*32 : 0;
    int jend   = jh ? ncand : h32*32;

    int tid  = threadIdx.x;
    int w    = tid >> 5, lane = tid & 31;
    int jpart = w >> 1;                       // 0: rows 0-7, 1: rows 8-15
    int slot = lane & 15;
    int head = ((w & 1) << 1) | (lane >> 4);
    int slice = jh*2 + jpart;

    if (jstart >= jend) {               // empty half: write zero partials
        for (int q0 = qt*16; q0 < ccount; q0 += 32) {
            if ((q0 + slot) < ccount) {
                int qi = g_ord[b][cstart + q0 + slot];
                int t = b*CN + qi;
                int pidx = (slice*CM + t)*CH + head;
                g_pl[pidx] = 0.f;
                ulonglong2* ap = (ulonglong2*)&g_pacc[(ull)pidx*32];
                ulonglong2 z; z.x = 0ull; z.y = 0ull;
                #pragma unroll
                for (int u = 0; u < 8; ++u) ap[u] = z;
            }
        }
        return;
    }
    int ntiles = (jend - jstart + TJR - 1) / TJR;

    unsigned sb = smem_u32(smn);

    // scale folded with log2(e): softmax exp(s) = exp2(s * log2e)
    const float scale = 0.17677669529663687f * 1.4426950408889634f;
    const float R2 = 0.0625f;
    ull scale2 = fpack2(scale, scale);

    for (int q0 = qt*16; q0 < ccount; q0 += 32) {
        bool active = (q0 + slot) < ccount;
        int qidx = active ? (q0 + slot) : 0;
        int qi = g_ord[b][cstart + qidx];
        int t = b*CN + qi;

        ull qr2[16];
        const ulonglong2* qp = (const ulonglong2*)&qkv[t*3*CD + head*CHD];
        #pragma unroll
        for (int u = 0; u < 8; ++u) {
            ulonglong2 qq = qp[u];
            qr2[2*u]   = fmul2(qq.x, scale2);
            qr2[2*u+1] = fmul2(qq.y, scale2);
        }
        float2 pi  = ((const float2*)pos)[t];
        float  sqi = sqv[t];

        float l = 0.f;
        ull acc2[16];
        #pragma unroll
        for (int u = 0; u < 16; ++u) acc2[u] = 0ull;

        // prologue: stage tile 0 (4 warps x 4 rows)
        {
            int ts = jstart;
            #pragma unroll
            for (int rr = 0; rr < TJR/4; ++rr) {
                int r = w + rr*4;
                int tj = b*CN + cand[ts + r];
                const char* gk = (const char*)&qkv[tj*3*CD + CD];
                const char* gv = (const char*)&qkv[tj*3*CD + 2*CD];
                cp16(sb + (KS_OFF + r*128)*4 + lane*16, gk + lane*16);
                cp16(sb + (VS_OFF + r*128)*4 + lane*16, gv + lane*16);
            }
            if (tid < TJR) {
                cp8(sb + (PS_OFF + tid*2)*4, &g_cpos[cbase + ts + tid]);
                cp4(sb + (SS_OFF + tid)*4,   &g_csq [cbase + ts + tid]);
            }
            asm volatile("cp.async.commit_group;" ::: "memory");
        }

        for (int tl = 0; tl < ntiles; ++tl) {
            int cur = tl & 1;
            if (tl + 1 < ntiles) {
                int nb2 = (tl + 1) & 1;
                int ts = jstart + (tl+1)*TJR;
                #pragma unroll
                for (int rr = 0; rr < TJR/4; ++rr) {
                    int r = w + rr*4;
                    int tj = b*CN + cand[ts + r];
                    const char* gk = (const char*)&qkv[tj*3*CD + CD];
                    const char* gv = (const char*)&qkv[tj*3*CD + 2*CD];
                    cp16(sb + (KS_OFF + nb2*TJR*128 + r*128)*4 + lane*16, gk + lane*16);
                    cp16(sb + (VS_OFF + nb2*TJR*128 + r*128)*4 + lane*16, gv + lane*16);
                }
                if (tid < TJR) {
                    cp8(sb + (PS_OFF + nb2*2*TJR + tid*2)*4, &g_cpos[cbase + ts + tid]);
                    cp4(sb + (SS_OFF + nb2*TJR + tid)*4,     &g_csq [cbase + ts + tid]);
                }
                asm volatile("cp.async.commit_group;" ::: "memory");
                asm volatile("cp.async.wait_group 1;" ::: "memory");
            } else {
                asm volatile("cp.async.wait_group 0;" ::: "memory");
            }
            __syncthreads();

            const float*  Kb = smn + KS_OFF + cur*TJR*128;
            const float*  Vb = smn + VS_OFF + cur*TJR*128;
            const float2* Pb = (const float2*)(smn + PS_OFF + cur*2*TJR);
            const float*  Sb = smn + SS_OFF + cur*TJR;

            #pragma unroll
            for (int j0j = 0; j0j < TJR/2; ++j0j) {
                int j = jpart*(TJR/2) + j0j;
                float2 pj = Pb[j];
                float d2 = sqi + Sb[j] - 2.f*(pi.x*pj.x + pi.y*pj.y);
                bool inw = (d2 <= R2);

                const ulonglong2* kr = (const ulonglong2*)&Kb[j*128 + (head<<5)];
                ulonglong2 k0v = kr[0], k1v = kr[1], k2v = kr[2], k3v = kr[3];
                ull sa  = fmul2(qr2[0],  k0v.x);
                ull sb2 = fmul2(qr2[1],  k0v.y);
                ull sc2 = fmul2(qr2[2],  k1v.x);
                ull sd  = fmul2(qr2[3],  k1v.y);
                sa  = ffma2(qr2[4],  k2v.x, sa);
                sb2 = ffma2(qr2[5],  k2v.y, sb2);
                sc2 = ffma2(qr2[6],  k3v.x, sc2);
                sd  = ffma2(qr2[7],  k3v.y, sd);
                ulonglong2 k4v = kr[4], k5v = kr[5], k6v = kr[6], k7v = kr[7];
                sa  = ffma2(qr2[8],  k4v.x, sa);
                sb2 = ffma2(qr2[9],  k4v.y, sb2);
                sc2 = ffma2(qr2[10], k5v.x, sc2);
                sd  = ffma2(qr2[11], k5v.y, sd);
                sa  = ffma2(qr2[12], k6v.x, sa);
                sb2 = ffma2(qr2[13], k6v.y, sb2);
                sc2 = ffma2(qr2[14], k7v.x, sc2);
                sd  = ffma2(qr2[15], k7v.y, sd);
                float sl, sh;
                funpack2(fadd2(fadd2(sa, sb2), fadd2(sc2, sd)), sl, sh);
                float s = sl + sh;

                float pb = inw ? exp2f(s) : 0.f;
                l += pb;
                ull pb2 = fpack2(pb, pb);
                const ulonglong2* vr = (const ulonglong2*)&Vb[j*128 + (head<<5)];
                #pragma unroll
                for (int u = 0; u < 8; ++u) {
                    ulonglong2 vv = vr[u];
                    acc2[2*u]   = ffma2(pb2, vv.x, acc2[2*u]);
                    acc2[2*u+1] = ffma2(pb2, vv.y, acc2[2*u+1]);
                }
            }
            __syncthreads();
        }

        if (active) {
            int pidx = (slice*CM + t)*CH + head;
            g_pl[pidx] = l;
            ulonglong2* ap = (ulonglong2*)&g_pacc[(ull)pidx*32];
            #pragma unroll
            for (int u = 0; u < 8; ++u) {
                ulonglong2 wv; wv.x = acc2[2*u]; wv.y = acc2[2*u+1];
                ap[u] = wv;
            }
        }
    }
}

// ---------------- launch ----------------------------------------------------
extern "C" void kernel_launch(void* const* d_in, const int* in_sizes, int n_in,
                              void* d_out, int out_size) {
    const float* x    = (const float*)d_in[0];
    const float* pos  = (const float*)d_in[1];
    const float* Wq_w = (const float*)d_in[2];
    const float* Wq_b = (const float*)d_in[3];
    const float* Wk_w = (const float*)d_in[4];
    const float* Wk_b = (const float*)d_in[5];
    const float* Wv_w = (const float*)d_in[6];
    const float* Wv_b = (const float*)d_in[7];
    const float* Wo_w = (const float*)d_in[8];
    const float* Wo_b = (const float*)d_in[9];
    const float* n1_g = (const float*)d_in[10];
    const float* n1_b = (const float*)d_in[11];
    const float* n2_g = (const float*)d_in[12];
    const float* n2_b = (const float*)d_in[13];
    const float* l1_w = (const float*)d_in[14];
    const float* l1_b = (const float*)d_in[15];
    const float* l2_w = (const float*)d_in[16];
    const float* l2_b = (const float*)d_in[17];
    float* out = (float*)d_out;

    float *gx, *gqkv, *ghid, *gwqkv, *gbqkv, *gwl1, *gbl1, *gsq, *gpartf;
    cudaGetSymbolAddress((void**)&gx,    g_x);
    cudaGetSymbolAddress((void**)&gqkv,  g_qkv);
    cudaGetSymbolAddress((void**)&ghid,  g_hid);
    cudaGetSymbolAddress((void**)&gpartf,g_partf);
    cudaGetSymbolAddress((void**)&gwqkv, g_wqkv);
    cudaGetSymbolAddress((void**)&gbqkv, g_bqkv);
    cudaGetSymbolAddress((void**)&gwl1,  g_wl1);
    cudaGetSymbolAddress((void**)&gbl1,  g_bl1);
    cudaGetSymbolAddress((void**)&gsq,   g_sq);

    cudaFuncSetAttribute(gemm_tc_kernel,
                         cudaFuncAttributeMaxDynamicSharedMemorySize, GEMM_SMEM);
    cudaFuncSetAttribute(attn_kernel,
                         cudaFuncAttributeMaxDynamicSharedMemorySize, ATTN_SMEM);

    dim3 gP(CM/128, CD/64);
    dim3 gQKV(CM/128, 3*CD/64);
    dim3 gF(CM/128, 2*CD/64);

    bin_kernel<<<1, 1024>>>(pos);
    build_cands_kernel<<<CB*NC2/4, 128>>>(pos);

    for (int i = 0; i < 2; ++i) {
        const float* xin = (i == 0) ? x : gx;

        // --- attention block (BN folded into QKV weights) ---
        bn_stats_kernel<<<NPART, 128>>>(xin, gpartf);
        xform_qkv_kernel<<<6, 256>>>(Wq_w + i*CD*CD, Wk_w + i*CD*CD, Wv_w + i*CD*CD,
                                     Wq_b + i*CD, Wk_b + i*CD, Wv_b + i*CD,
                                     n1_g + i*CD, n1_b + i*CD);
        gemm_tc_kernel<<<gQKV, 256, GEMM_SMEM>>>(xin, gwqkv, gbqkv, nullptr, gqkv,
                                                 CM, CD, 3*CD, 0, 0);
        if (i == 0)
            rope_kernel<<<(CM*64 + 255)/256, 256>>>(gqkv, pos);

        attn_kernel<<<dim3(NC2, 2, CB*2), 128, ATTN_SMEM>>>(gqkv, pos, gsq);
        // layer 0 reads residual directly from input x (copy_kernel eliminated)
        gemm_tc_kernel<<<gP, 256, GEMM_SMEM>>>(nullptr, Wo_w + i*CD*CD, Wo_b + i*CD,
                                               xin, gx, CM, CD, CD, 0, 1);

        // --- FFN block (BN folded into l1 weights) ---
        bn_stats_kernel<<<NPART, 128>>>(gx, gpartf);
        xform_l1_kernel<<<4, 256>>>(l1_w + i*CD*2*CD, l1_b + i*2*CD,
                                    n2_g + i*CD, n2_b + i*CD);
        gemm_tc_kernel<<<gF, 256, GEMM_SMEM>>>(gx, gwl1, gbl1, nullptr, ghid,
                                               CM, CD, 2*CD, 1, 0);
        float* dst = (i == 1) ? out : gx;
        gemm_tc_kernel<<<gP, 256, GEMM_SMEM>>>(ghid, l2_w + i*2*CD*CD, l2_b + i*CD,
                                               gx, dst, CM, 2*CD, CD, 0, 0);
    }
}

// round 17
// speedup vs baseline: 1.2229x; 1.1943x over previous
#include <cuda_runtime.h>
#include <math_constants.h>

#define CB 2
#define CN 4096
#define CD 128
#define CH 4
#define CHD 32
#define CM (CB*CN)   // 8192 tokens
#define NCELL 16
#define NC2 (NCELL*NCELL)
#define CAND_CAP 2048
#define NPART 256    // bn_stats partial blocks
#define NSLICE 4     // attention partial slices: 2 j-halves x 2 jparts

typedef unsigned long long ull;

// ---------------- f32x2 packed helpers (sm_100+ PTX) -----------------------
__device__ __forceinline__ ull ffma2(ull a, ull b, ull c) {
    ull d; asm("fma.rn.f32x2 %0,%1,%2,%3;" : "=l"(d) : "l"(a), "l"(b), "l"(c)); return d;
}
__device__ __forceinline__ ull fmul2(ull a, ull b) {
    ull d; asm("mul.rn.f32x2 %0,%1,%2;" : "=l"(d) : "l"(a), "l"(b)); return d;
}
__device__ __forceinline__ ull fadd2(ull a, ull b) {
    ull d; asm("add.rn.f32x2 %0,%1,%2;" : "=l"(d) : "l"(a), "l"(b)); return d;
}
__device__ __forceinline__ ull fpack2(float lo, float hi) {
    ull d; asm("mov.b64 %0,{%1,%2};" : "=l"(d) : "f"(lo), "f"(hi)); return d;
}
__device__ __forceinline__ void funpack2(ull a, float& lo, float& hi) {
    asm("mov.b64 {%0,%1},%2;" : "=f"(lo), "=f"(hi) : "l"(a));
}

// ---------------- cp.async helpers ------------------------------------------
__device__ __forceinline__ unsigned smem_u32(const void* p) {
    unsigned a;
    asm("{ .reg .u64 t; cvta.to.shared.u64 t, %1; cvt.u32.u64 %0, t; }" : "=r"(a) : "l"(p));
    return a;
}
__device__ __forceinline__ void cp16(unsigned s, const void* g) {
    asm volatile("cp.async.cg.shared.global [%0], [%1], 16;" :: "r"(s), "l"(g));
}
__device__ __forceinline__ void cp8(unsigned s, const void* g) {
    asm volatile("cp.async.ca.shared.global [%0], [%1], 8;" :: "r"(s), "l"(g));
}
__device__ __forceinline__ void cp4(unsigned s, const void* g) {
    asm volatile("cp.async.ca.shared.global [%0], [%1], 4;" :: "r"(s), "l"(g));
}

// ---------------- tf32 split helpers ----------------------------------------
__device__ __forceinline__ void tf32split(float x, float& hi, float& lo) {
    unsigned h;
    asm("cvt.rna.tf32.f32 %0, %1;" : "=r"(h) : "f"(x));
    float hf = __uint_as_float(h);
    float l = x - hf;
    unsigned lb;
    asm("cvt.rna.tf32.f32 %0, %1;" : "=r"(lb) : "f"(l));
    hi = hf; lo = __uint_as_float(lb);
}

__device__ __forceinline__ void mma_tf32(float* c, const unsigned* a, const unsigned* b) {
    asm volatile(
        "mma.sync.aligned.m16n8k8.row.col.f32.tf32.tf32.f32 "
        "{%0,%1,%2,%3},{%4,%5,%6,%7},{%8,%9},{%0,%1,%2,%3};\n"
        : "+f"(c[0]), "+f"(c[1]), "+f"(c[2]), "+f"(c[3])
        : "r"(a[0]), "r"(a[1]), "r"(a[2]), "r"(a[3]), "r"(b[0]), "r"(b[1]));
}

// ---------------- scratch ---------------------------------------------------
__device__ float  g_x   [CM*CD];
__device__ float  g_qkv [CM*3*CD];
__device__ float  g_hid [CM*2*CD];
__device__ float  g_partf[NPART*2*CD];
__device__ float  g_sq  [CM];
__device__ float  g_wqkv[CD*3*CD];
__device__ float  g_bqkv[3*CD];
__device__ float  g_wl1 [CD*2*CD];
__device__ float  g_bl1 [2*CD];
__device__ int    g_cstart[CB][NC2+1];
__device__ int    g_ord   [CB][CN];
__device__ int    g_cand  [CB*NC2*CAND_CAP];
__device__ float2 g_cpos  [CB*NC2*CAND_CAP];
__device__ float  g_csq   [CB*NC2*CAND_CAP];
__device__ int    g_ncand [CB*NC2];
// attention partials: [slice][token][head]
__device__ float g_pl  [NSLICE*CM*CH];
__device__ float g_pacc[NSLICE*CM*CH*32];

// ---------------- fused binning: hist + scan + scatter (one block) ----------
__global__ void __launch_bounds__(1024)
bin_kernel(const float* __restrict__ pos) {
    __shared__ int scnt[CB*NC2];
    __shared__ int scur[CB*NC2];
    int tid = threadIdx.x;
    if (tid < CB*NC2) scnt[tid] = 0;
    __syncthreads();
    int mycell[8], mytok[8];
    #pragma unroll
    for (int i = 0; i < 8; ++i) {
        int t = tid + i*1024;
        int b = t >> 12, n = t & (CN-1);
        float px = pos[2*t], py = pos[2*t+1];
        int cx = min(NCELL-1, max(0, (int)(px * NCELL)));
        int cy = min(NCELL-1, max(0, (int)(py * NCELL)));
        int c = cy*NCELL + cx;
        g_sq[t] = px*px + py*py;
        mycell[i] = b*NC2 + c;
        mytok[i]  = n;
        atomicAdd(&scnt[b*NC2 + c], 1);
    }
    __syncthreads();
    int v = (tid < CB*NC2) ? scnt[tid] : 0;
    for (int off = 1; off < NC2; off <<= 1) {
        int t2 = 0;
        if (tid < CB*NC2 && (tid & (NC2-1)) >= off) t2 = scnt[tid-off];
        __syncthreads();
        if (tid < CB*NC2) scnt[tid] += t2;
        __syncthreads();
    }
    if (tid < CB*NC2) {
        int incl = scnt[tid];
        int excl = incl - v;
        int b = tid >> 8, c = tid & (NC2-1);
        g_cstart[b][c] = excl;
        scur[tid] = excl;
        if (c == NC2-1) g_cstart[b][NC2] = incl;
    }
    __syncthreads();
    #pragma unroll
    for (int i = 0; i < 8; ++i) {
        int r = atomicAdd(&scur[mycell[i]], 1);
        int b = mycell[i] >> 8;
        g_ord[b][r] = mytok[i];
    }
}

// ---------------- candidate list build: one warp per (b,cell) ---------------
__global__ void __launch_bounds__(128)
build_cands_kernel(const float* __restrict__ pos) {
    int wid = threadIdx.x >> 5, lane = threadIdx.x & 31;
    int cidx = blockIdx.x * 4 + wid;
    int b = cidx >> 8, cell = cidx & (NC2-1);
    int cx = cell & (NCELL-1), cy = cell >> 4;
    float X0 = cx * (1.f/NCELL), X1 = (cx+1) * (1.f/NCELL);
    float Y0 = cy * (1.f/NCELL), Y1 = (cy+1) * (1.f/NCELL);
    const float R2m = 0.0625f + 1e-4f;
    int base = cidx * CAND_CAP;
    int* dst = &g_cand[base];
    int cnt = 0;
    for (int dy = -5; dy <= 5; ++dy) {
        int yy = cy + dy;
        if (yy < 0 || yy >= NCELL) continue;
        int bb = abs(dy) > 1 ? abs(dy) - 1 : 0;
        int rem = 16 - bb*bb;
        if (rem < 0) continue;
        int kx = (int)floorf(sqrtf((float)rem)) + 1;
        int x0 = cx - kx; if (x0 < 0) x0 = 0;
        int x1 = cx + kx; if (x1 > NCELL-1) x1 = NCELL-1;
        int S = g_cstart[b][yy*NCELL + x0];
        int E = g_cstart[b][yy*NCELL + x1 + 1];
        for (int j0 = S; j0 < E; j0 += 32) {
            int src = j0 + lane;
            bool keep = false; int tok = 0; float2 p = make_float2(0.f, 0.f);
            if (src < E) {
                tok = g_ord[b][src];
                p = ((const float2*)pos)[b*CN + tok];
                float ddx = fmaxf(fmaxf(X0 - p.x, p.x - X1), 0.f);
                float ddy = fmaxf(fmaxf(Y0 - p.y, p.y - Y1), 0.f);
                keep = (ddx*ddx + ddy*ddy) <= R2m;
            }
            unsigned bal = __ballot_sync(0xFFFFFFFFu, keep);
            int ofs = __popc(bal & ((1u << lane) - 1));
            if (keep && cnt + ofs < CAND_CAP) {
                int w = cnt + ofs;
                dst[w] = tok;
                g_cpos[base + w] = p;
                g_csq[base + w] = p.x*p.x + p.y*p.y;
            }
            cnt += __popc(bal);
        }
    }
    if (cnt > CAND_CAP) cnt = CAND_CAP;
    int padded = (cnt + 31) & ~31;
    if (padded > CAND_CAP) padded = CAND_CAP;
    for (int i2 = cnt + lane; i2 < padded; i2 += 32) {
        dst[i2] = 0;
        g_cpos[base + i2] = make_float2(0.f, 0.f);
        g_csq[base + i2] = CUDART_INF_F;
    }
    if (lane == 0) g_ncand[cidx] = padded;
}

// ---------------- BatchNorm stats (fp32 partials, wide grid) -----------------
__global__ void __launch_bounds__(128)
bn_stats_kernel(const float* __restrict__ x, float* __restrict__ part) {
    int d = threadIdx.x;
    int blk = blockIdx.x;
    int r0 = blk * (CM / NPART);
    float s = 0.f, s2 = 0.f;
    #pragma unroll 8
    for (int r = 0; r < CM/NPART; ++r) {
        float v = x[(r0 + r)*CD + d];
        s  += v;
        s2 += v*v;
    }
    part[blk*2*CD + d]      = s;
    part[blk*2*CD + CD + d] = s2;
}

// ---------------- BN finalize (fp32 4-chain; fp64 was 18.4cyc/op poison) -----
__device__ __forceinline__ void bn_finalize_smem(const float* gam, const float* bet,
                                                 float* sa, float* sc, int tid) {
    if (tid < CD) {
        float s0=0.f,s1=0.f,s2f=0.f,s3=0.f,q0=0.f,q1=0.f,q2=0.f,q3=0.f;
        #pragma unroll 4
        for (int b2 = 0; b2 < NPART; b2 += 4) {
            s0 += g_partf[(b2+0)*2*CD + tid];  q0 += g_partf[(b2+0)*2*CD + CD + tid];
            s1 += g_partf[(b2+1)*2*CD + tid];  q1 += g_partf[(b2+1)*2*CD + CD + tid];
            s2f+= g_partf[(b2+2)*2*CD + tid];  q2 += g_partf[(b2+2)*2*CD + CD + tid];
            s3 += g_partf[(b2+3)*2*CD + tid];  q3 += g_partf[(b2+3)*2*CD + CD + tid];
        }
        float s  = (s0+s1)+(s2f+s3);
        float sq = (q0+q1)+(q2+q3);
        float m   = s * (1.f/(float)CM);
        float var = sq * (1.f/(float)CM) - m*m;
        float rstd = rsqrtf(var + 1e-5f);
        float a = rstd * gam[tid];
        sa[tid] = a;
        sc[tid] = bet[tid] - m * a;
    }
}

__global__ void __launch_bounds__(256)
xform_qkv_kernel(const float* __restrict__ Wq, const float* __restrict__ Wk,
                 const float* __restrict__ Wv,
                 const float* __restrict__ bq, const float* __restrict__ bk,
                 const float* __restrict__ bv,
                 const float* __restrict__ gam, const float* __restrict__ bet) {
    __shared__ float sa[CD], sc[CD];
    int tid = threadIdx.x;
    bn_finalize_smem(gam, bet, sa, sc, tid);
    __syncthreads();
    int nb = blockIdx.x * 64;
    {
        int n = nb + (tid & 63);
        int sel = n >> 7, ci = n & (CD-1);
        const float* W = (sel == 0) ? Wq : (sel == 1) ? Wk : Wv;
        for (int k = tid >> 6; k < CD; k += 4)
            g_wqkv[k*384 + n] = sa[k] * W[k*CD + ci];
    }
    if (tid < 64) {
        int n2 = nb + tid;
        int sel2 = n2 >> 7, ci2 = n2 & (CD-1);
        const float* W2 = (sel2 == 0) ? Wq : (sel2 == 1) ? Wk : Wv;
        const float* bb = (sel2 == 0) ? bq : (sel2 == 1) ? bk : bv;
        float s = 0.f;
        #pragma unroll 4
        for (int k = 0; k < CD; ++k) s += sc[k] * W2[k*CD + ci2];
        g_bqkv[n2] = bb[ci2] + s;
    }
}

__global__ void __launch_bounds__(256)
xform_l1_kernel(const float* __restrict__ W, const float* __restrict__ bias,
                const float* __restrict__ gam, const float* __restrict__ bet) {
    __shared__ float sa[CD], sc[CD];
    int tid = threadIdx.x;
    bn_finalize_smem(gam, bet, sa, sc, tid);
    __syncthreads();
    int nb = blockIdx.x * 64;
    {
        int n = nb + (tid & 63);
        for (int k = tid >> 6; k < CD; k += 4)
            g_wl1[k*(2*CD) + n] = sa[k] * W[k*(2*CD) + n];
    }
    if (tid < 64) {
        int n2 = nb + tid;
        float s = 0.f;
        #pragma unroll 4
        for (int k = 0; k < CD; ++k) s += sc[k] * W[k*(2*CD) + n2];
        g_bl1[n2] = bias[n2] + s;
    }
}

// ---------------- RoPE (layer 0 only) ---------------------------------------
__global__ void rope_kernel(float* __restrict__ qkv, const float* __restrict__ pos) {
    int idx = blockIdx.x * blockDim.x + threadIdx.x;
    if (idx >= CM * 64) return;
    int p = idx & 63;
    int t = idx >> 6;
    int group = p >> 5;
    int fidx  = p & 31;
    float freq = 3.14159265358979324f * (float)(fidx + 1);
    float ang = pos[t*2 + group] * freq;
    float sv, cv;
    sincosf(ang, &sv, &cv);
    int qb = t*3*CD + (p << 1);
    float q0 = qkv[qb], q1 = qkv[qb+1];
    qkv[qb]   = cv*q0 - sv*q1;
    qkv[qb+1] = cv*q1 + sv*q0;
    int kb = qb + CD;
    float k0 = qkv[kb], k1 = qkv[kb+1];
    qkv[kb]   = cv*k0 - sv*k1;
    qkv[kb+1] = cv*k1 + sv*k0;
}

// ---------------- tensor-core GEMM (3xTF32) ---------------------------------
#define AS_STR 36
#define BS_STR 72
#define SM_AHI 0
#define SM_ALO (128*AS_STR)
#define SM_BHI (2*128*AS_STR)
#define SM_BLO (2*128*AS_STR + 32*BS_STR)
#define GEMM_SMEM ((2*128*AS_STR + 2*32*BS_STR)*4)

__global__ void __launch_bounds__(256)
gemm_tc_kernel(const float* __restrict__ A, const float* __restrict__ W,
               const float* __restrict__ bias, const float* __restrict__ resid,
               float* __restrict__ C, int M, int K, int Nout, int relu, int mergeA) {
    extern __shared__ float sm[];
    float* As_hi = sm + SM_AHI;
    float* As_lo = sm + SM_ALO;
    float* Bs_hi = sm + SM_BHI;
    float* Bs_lo = sm + SM_BLO;

    int tid = threadIdx.x;
    int lane = tid & 31, warp = tid >> 5;
    int wm = warp & 3, wn = warp >> 2;
    int m_w = wm*32, n_w = wn*32;
    int g = lane >> 2, t = lane & 3;

    int bm0 = blockIdx.x * 128, bn0 = blockIdx.y * 64;

    float acc[2][4][4];
    #pragma unroll
    for (int i = 0; i < 2; ++i)
        #pragma unroll
        for (int j = 0; j < 4; ++j)
            #pragma unroll
            for (int u = 0; u < 4; ++u) acc[i][j][u] = 0.f;

    for (int k0 = 0; k0 < K; k0 += 32) {
        __syncthreads();
        #pragma unroll
        for (int it = 0; it < 4; ++it) {
            int f = tid + it*256;
            int row = f >> 3, c4 = (f & 7) << 2;
            float4 ga;
            if (mergeA) {
                int t_tok = bm0 + row;
                int kcol = k0 + c4;
                int head = kcol >> 5, d0 = kcol & 31;
                int i0 = t_tok*CH + head;
                float lsum = 0.f;
                float4 vs = make_float4(0.f, 0.f, 0.f, 0.f);
                #pragma unroll
                for (int sl2 = 0; sl2 < NSLICE; ++sl2) {
                    float4 v = *(const float4*)&g_pacc[((ull)sl2*CM*CH + i0)*32 + d0];
                    vs.x += v.x; vs.y += v.y; vs.z += v.z; vs.w += v.w;
                    lsum += g_pl[sl2*CM*CH + i0];
                }
                float f0 = 1.f / lsum;
                ga.x = vs.x*f0; ga.y = vs.y*f0; ga.z = vs.z*f0; ga.w = vs.w*f0;
            } else {
                ga = *(const float4*)&A[(bm0 + row)*K + k0 + c4];
            }
            float4 h4, l4;
            tf32split(ga.x, h4.x, l4.x);
            tf32split(ga.y, h4.y, l4.y);
            tf32split(ga.z, h4.z, l4.z);
            tf32split(ga.w, h4.w, l4.w);
            *(float4*)&As_hi[row*AS_STR + c4] = h4;
            *(float4*)&As_lo[row*AS_STR + c4] = l4;
        }
        #pragma unroll
        for (int it = 0; it < 2; ++it) {
            int f = tid + it*256;
            int row = f >> 4, c4 = (f & 15) << 2;
            float4 gb = *(const float4*)&W[(k0 + row)*Nout + bn0 + c4];
            float4 h4, l4;
            tf32split(gb.x, h4.x, l4.x);
            tf32split(gb.y, h4.y, l4.y);
            tf32split(gb.z, h4.z, l4.z);
            tf32split(gb.w, h4.w, l4.w);
            *(float4*)&Bs_hi[row*BS_STR + c4] = h4;
            *(float4*)&Bs_lo[row*BS_STR + c4] = l4;
        }
        __syncthreads();

        #pragma unroll
        for (int k8 = 0; k8 < 32; k8 += 8) {
            unsigned ah[2][4], al[2][4];
            #pragma unroll
            for (int mt = 0; mt < 2; ++mt) {
                int base = (m_w + mt*16 + g)*AS_STR + k8 + t;
                ah[mt][0] = __float_as_uint(As_hi[base]);
                ah[mt][1] = __float_as_uint(As_hi[base + 8*AS_STR]);
                ah[mt][2] = __float_as_uint(As_hi[base + 4]);
                ah[mt][3] = __float_as_uint(As_hi[base + 8*AS_STR + 4]);
                al[mt][0] = __float_as_uint(As_lo[base]);
                al[mt][1] = __float_as_uint(As_lo[base + 8*AS_STR]);
                al[mt][2] = __float_as_uint(As_lo[base + 4]);
                al[mt][3] = __float_as_uint(As_lo[base + 8*AS_STR + 4]);
            }
            unsigned bh[4][2], bl[4][2];
            #pragma unroll
            for (int nt = 0; nt < 4; ++nt) {
                int base = (k8 + t)*BS_STR + n_w + nt*8 + g;
                bh[nt][0] = __float_as_uint(Bs_hi[base]);
                bh[nt][1] = __float_as_uint(Bs_hi[base + 4*BS_STR]);
                bl[nt][0] = __float_as_uint(Bs_lo[base]);
                bl[nt][1] = __float_as_uint(Bs_lo[base + 4*BS_STR]);
            }
            #pragma unroll
            for (int mt = 0; mt < 2; ++mt)
                #pragma unroll
                for (int nt = 0; nt < 4; ++nt) {
                    mma_tf32(acc[mt][nt], al[mt], bh[nt]);
                    mma_tf32(acc[mt][nt], ah[mt], bl[nt]);
                    mma_tf32(acc[mt][nt], ah[mt], bh[nt]);
                }
        }
    }

    #pragma unroll
    for (int mt = 0; mt < 2; ++mt) {
        #pragma unroll
        for (int nt = 0; nt < 4; ++nt) {
            int row0 = bm0 + m_w + mt*16 + g;
            int col  = bn0 + n_w + nt*8 + 2*t;
            float2 bv = *(const float2*)&bias[col];
            float2 r0, r1;
            r0.x = acc[mt][nt][0] + bv.x;  r0.y = acc[mt][nt][1] + bv.y;
            r1.x = acc[mt][nt][2] + bv.x;  r1.y = acc[mt][nt][3] + bv.y;
            if (resid) {
                float2 v0 = *(const float2*)&resid[row0*Nout + col];
                float2 v1 = *(const float2*)&resid[(row0+8)*Nout + col];
                r0.x += v0.x; r0.y += v0.y;
                r1.x += v1.x; r1.y += v1.y;
            }
            if (relu) {
                r0.x = fmaxf(r0.x, 0.f); r0.y = fmaxf(r0.y, 0.f);
                r1.x = fmaxf(r1.x, 0.f); r1.y = fmaxf(r1.y, 0.f);
            }
            *(float2*)&C[row0*Nout + col]     = r0;
            *(float2*)&C[(row0+8)*Nout + col] = r1;
        }
    }
}

// ---------------- attention: 128 threads, warp-pair j-split -----------------
// grid (NC2, 2 qtiles, CB*2 jhalf); 128 threads = 2 jparts x (16 slots x 4 heads).
#define TJR 16
#define KS_OFF 0
#define VS_OFF (2*TJR*128)
#define PS_OFF (4*TJR*128)
#define SS_OFF (4*TJR*128 + 2*2*TJR)
#define ATTN_SMEM ((4*TJR*128 + 2*2*TJR + 2*TJR)*4)

__global__ void __launch_bounds__(128)
attn_kernel(const float* __restrict__ qkv, const float* __restrict__ pos,
            const float* __restrict__ sqv) {
    extern __shared__ float smn[];

    int cell = blockIdx.x, qt = blockIdx.y;
    int b = blockIdx.z >> 1, jh = blockIdx.z & 1;
    int cidx = b*NC2 + cell;
    int cstart = g_cstart[b][cell];
    int ccount = g_cstart[b][cell+1] - cstart;
    if (qt*16 >= ccount) return;

    int ncand = g_ncand[cidx];          // multiple of 32
    int cbase = cidx*CAND_CAP;
    const int* cand = &g_cand[cbase];
    int nt32 = ncand >> 5;
    int h32 = (nt32 + 1) >> 1;
    int jstart = jh ? h32*32 : 0;
    int jend   = jh ? ncand : h32*32;

    int tid  = threadIdx.x;
    int w    = tid >> 5, lane = tid & 31;
    int jpart = w >> 1;                       // 0: rows 0-7, 1: rows 8-15
    int slot = lane & 15;
    int head = ((w & 1) << 1) | (lane >> 4);
    int slice = jh*2 + jpart;

    if (jstart >= jend) {               // empty half: write zero partials
        for (int q0 = qt*16; q0 < ccount; q0 += 32) {
            if ((q0 + slot) < ccount) {
                int qi = g_ord[b][cstart + q0 + slot];
                int t = b*CN + qi;
                int pidx = (slice*CM + t)*CH + head;
                g_pl[pidx] = 0.f;
                ulonglong2* ap = (ulonglong2*)&g_pacc[(ull)pidx*32];
                ulonglong2 z; z.x = 0ull; z.y = 0ull;
                #pragma unroll
                for (int u = 0; u < 8; ++u) ap[u] = z;
            }
        }
        return;
    }
    int ntiles = (jend - jstart + TJR - 1) / TJR;

    unsigned sb = smem_u32(smn);

    // scale folded with log2(e): softmax exp(s) = exp2(s * log2e)
    const float scale = 0.17677669529663687f * 1.4426950408889634f;
    const float R2 = 0.0625f;
    ull scale2 = fpack2(scale, scale);

    for (int q0 = qt*16; q0 < ccount; q0 += 32) {
        bool active = (q0 + slot) < ccount;
        int qidx = active ? (q0 + slot) : 0;
        int qi = g_ord[b][cstart + qidx];
        int t = b*CN + qi;

        ull qr2[16];
        const ulonglong2* qp = (const ulonglong2*)&qkv[t*3*CD + head*CHD];
        #pragma unroll
        for (int u = 0; u < 8; ++u) {
            ulonglong2 qq = qp[u];
            qr2[2*u]   = fmul2(qq.x, scale2);
            qr2[2*u+1] = fmul2(qq.y, scale2);
        }
        float2 pi  = ((const float2*)pos)[t];
        float  sqi = sqv[t];

        float l = 0.f;
        ull acc2[16];
        #pragma unroll
        for (int u = 0; u < 16; ++u) acc2[u] = 0ull;

        // prologue: stage tile 0 (4 warps x 4 rows)
        {
            int ts = jstart;
            #pragma unroll
            for (int rr = 0; rr < TJR/4; ++rr) {
                int r = w + rr*4;
                int tj = b*CN + cand[ts + r];
                const char* gk = (const char*)&qkv[tj*3*CD + CD];
                const char* gv = (const char*)&qkv[tj*3*CD + 2*CD];
                cp16(sb + (KS_OFF + r*128)*4 + lane*16, gk + lane*16);
                cp16(sb + (VS_OFF + r*128)*4 + lane*16, gv + lane*16);
            }
            if (tid < TJR) {
                cp8(sb + (PS_OFF + tid*2)*4, &g_cpos[cbase + ts + tid]);
                cp4(sb + (SS_OFF + tid)*4,   &g_csq [cbase + ts + tid]);
            }
            asm volatile("cp.async.commit_group;" ::: "memory");
        }

        for (int tl = 0; tl < ntiles; ++tl) {
            int cur = tl & 1;
            if (tl + 1 < ntiles) {
                int nb2 = (tl + 1) & 1;
                int ts = jstart + (tl+1)*TJR;
                #pragma unroll
                for (int rr = 0; rr < TJR/4; ++rr) {
                    int r = w + rr*4;
                    int tj = b*CN + cand[ts + r];
                    const char* gk = (const char*)&qkv[tj*3*CD + CD];
                    const char* gv = (const char*)&qkv[tj*3*CD + 2*CD];
                    cp16(sb + (KS_OFF + nb2*TJR*128 + r*128)*4 + lane*16, gk + lane*16);
                    cp16(sb + (VS_OFF + nb2*TJR*128 + r*128)*4 + lane*16, gv + lane*16);
                }
                if (tid < TJR) {
                    cp8(sb + (PS_OFF + nb2*2*TJR + tid*2)*4, &g_cpos[cbase + ts + tid]);
                    cp4(sb + (SS_OFF + nb2*TJR + tid)*4,     &g_csq [cbase + ts + tid]);
                }
                asm volatile("cp.async.commit_group;" ::: "memory");
                asm volatile("cp.async.wait_group 1;" ::: "memory");
            } else {
                asm volatile("cp.async.wait_group 0;" ::: "memory");
            }
            __syncthreads();

            const float*  Kb = smn + KS_OFF + cur*TJR*128;
            const float*  Vb = smn + VS_OFF + cur*TJR*128;
            const float2* Pb = (const float2*)(smn + PS_OFF + cur*2*TJR);
            const float*  Sb = smn + SS_OFF + cur*TJR;

            #pragma unroll
            for (int j0j = 0; j0j < TJR/2; ++j0j) {
                int j = jpart*(TJR/2) + j0j;
                float2 pj = Pb[j];
                float d2 = sqi + Sb[j] - 2.f*(pi.x*pj.x + pi.y*pj.y);
                bool inw = (d2 <= R2);

                const ulonglong2* kr = (const ulonglong2*)&Kb[j*128 + (head<<5)];
                ulonglong2 k0v = kr[0], k1v = kr[1], k2v = kr[2], k3v = kr[3];
                ull sa  = fmul2(qr2[0],  k0v.x);
                ull sb2 = fmul2(qr2[1],  k0v.y);
                ull sc2 = fmul2(qr2[2],  k1v.x);
                ull sd  = fmul2(qr2[3],  k1v.y);
                sa  = ffma2(qr2[4],  k2v.x, sa);
                sb2 = ffma2(qr2[5],  k2v.y, sb2);
                sc2 = ffma2(qr2[6],  k3v.x, sc2);
                sd  = ffma2(qr2[7],  k3v.y, sd);
                ulonglong2 k4v = kr[4], k5v = kr[5], k6v = kr[6], k7v = kr[7];
                sa  = ffma2(qr2[8],  k4v.x, sa);
                sb2 = ffma2(qr2[9],  k4v.y, sb2);
                sc2 = ffma2(qr2[10], k5v.x, sc2);
                sd  = ffma2(qr2[11], k5v.y, sd);
                sa  = ffma2(qr2[12], k6v.x, sa);
                sb2 = ffma2(qr2[13], k6v.y, sb2);
                sc2 = ffma2(qr2[14], k7v.x, sc2);
                sd  = ffma2(qr2[15], k7v.y, sd);
                float sl, sh;
                funpack2(fadd2(fadd2(sa, sb2), fadd2(sc2, sd)), sl, sh);
                float s = sl + sh;

                float pb = inw ? exp2f(s) : 0.f;
                l += pb;
                ull pb2 = fpack2(pb, pb);
                const ulonglong2* vr = (const ulonglong2*)&Vb[j*128 + (head<<5)];
                #pragma unroll
                for (int u = 0; u < 8; ++u) {
                    ulonglong2 vv = vr[u];
                    acc2[2*u]   = ffma2(pb2, vv.x, acc2[2*u]);
                    acc2[2*u+1] = ffma2(pb2, vv.y, acc2[2*u+1]);
                }
            }
            __syncthreads();
        }

        if (active) {
            int pidx = (slice*CM + t)*CH + head;
            g_pl[pidx] = l;
            ulonglong2* ap = (ulonglong2*)&g_pacc[(ull)pidx*32];
            #pragma unroll
            for (int u = 0; u < 8; ++u) {
                ulonglong2 wv; wv.x = acc2[2*u]; wv.y = acc2[2*u+1];
                ap[u] = wv;
            }
        }
    }
}

// ---------------- launch ----------------------------------------------------
extern "C" void kernel_launch(void* const* d_in, const int* in_sizes, int n_in,
                              void* d_out, int out_size) {
    const float* x    = (const float*)d_in[0];
    const float* pos  = (const float*)d_in[1];
    const float* Wq_w = (const float*)d_in[2];
    const float* Wq_b = (const float*)d_in[3];
    const float* Wk_w = (const float*)d_in[4];
    const float* Wk_b = (const float*)d_in[5];
    const float* Wv_w = (const float*)d_in[6];
    const float* Wv_b = (const float*)d_in[7];
    const float* Wo_w = (const float*)d_in[8];
    const float* Wo_b = (const float*)d_in[9];
    const float* n1_g = (const float*)d_in[10];
    const float* n1_b = (const float*)d_in[11];
    const float* n2_g = (const float*)d_in[12];
    const float* n2_b = (const float*)d_in[13];
    const float* l1_w = (const float*)d_in[14];
    const float* l1_b = (const float*)d_in[15];
    const float* l2_w = (const float*)d_in[16];
    const float* l2_b = (const float*)d_in[17];
    float* out = (float*)d_out;

    float *gx, *gqkv, *ghid, *gwqkv, *gbqkv, *gwl1, *gbl1, *gsq, *gpartf;
    cudaGetSymbolAddress((void**)&gx,    g_x);
    cudaGetSymbolAddress((void**)&gqkv,  g_qkv);
    cudaGetSymbolAddress((void**)&ghid,  g_hid);
    cudaGetSymbolAddress((void**)&gpartf,g_partf);
    cudaGetSymbolAddress((void**)&gwqkv, g_wqkv);
    cudaGetSymbolAddress((void**)&gbqkv, g_bqkv);
    cudaGetSymbolAddress((void**)&gwl1,  g_wl1);
    cudaGetSymbolAddress((void**)&gbl1,  g_bl1);
    cudaGetSymbolAddress((void**)&gsq,   g_sq);

    cudaFuncSetAttribute(gemm_tc_kernel,
                         cudaFuncAttributeMaxDynamicSharedMemorySize, GEMM_SMEM);
    cudaFuncSetAttribute(attn_kernel,
                         cudaFuncAttributeMaxDynamicSharedMemorySize, ATTN_SMEM);

    dim3 gP(CM/128, CD/64);
    dim3 gQKV(CM/128, 3*CD/64);
    dim3 gF(CM/128, 2*CD/64);

    bin_kernel<<<1, 1024>>>(pos);
    build_cands_kernel<<<CB*NC2/4, 128>>>(pos);

    for (int i = 0; i < 2; ++i) {
        const float* xin = (i == 0) ? x : gx;

        // --- attention block (BN folded into QKV weights) ---
        bn_stats_kernel<<<NPART, 128>>>(xin, gpartf);
        xform_qkv_kernel<<<6, 256>>>(Wq_w + i*CD*CD, Wk_w + i*CD*CD, Wv_w + i*CD*CD,
                                     Wq_b + i*CD, Wk_b + i*CD, Wv_b + i*CD,
                                     n1_g + i*CD, n1_b + i*CD);
        gemm_tc_kernel<<<gQKV, 256, GEMM_SMEM>>>(xin, gwqkv, gbqkv, nullptr, gqkv,
                                                 CM, CD, 3*CD, 0, 0);
        if (i == 0)
            rope_kernel<<<(CM*64 + 255)/256, 256>>>(gqkv, pos);

        attn_kernel<<<dim3(NC2, 2, CB*2), 128, ATTN_SMEM>>>(gqkv, pos, gsq);
        gemm_tc_kernel<<<gP, 256, GEMM_SMEM>>>(nullptr, Wo_w + i*CD*CD, Wo_b + i*CD,
                                               xin, gx, CM, CD, CD, 0, 1);

        // --- FFN block (BN folded into l1 weights) ---
        bn_stats_kernel<<<NPART, 128>>>(gx, gpartf);
        xform_l1_kernel<<<4, 256>>>(l1_w + i*CD*2*CD, l1_b + i*2*CD,
                                    n2_g + i*CD, n2_b + i*CD);
        gemm_tc_kernel<<<gF, 256, GEMM_SMEM>>>(gx, gwl1, gbl1, nullptr, ghid,
                                               CM, CD, 2*CD, 1, 0);
        float* dst = (i == 1) ? out : gx;
        gemm_tc_kernel<<<gP, 256, GEMM_SMEM>>>(ghid, l2_w + i*2*CD*CD, l2_b + i*CD,
                                               gx, dst, CM, 2*CD, CD, 0, 0);
    }
}